// round 1
// baseline (speedup 1.0000x reference)
#include <cuda_runtime.h>

#define BB 4
#define TT 2048
#define DD 1024
#define HH 16
#define HD 64
#define NR (BB*TT)   // 8192

// Scratch (device globals: allocation-free rule)
__device__ float g_xn[NR*DD];   // layernormed x, [B*T, D]
__device__ float g_q[NR*DD];    // [B,H,T,HD]
__device__ float g_k[NR*DD];    // [B,H,T,HD]
__device__ float g_v[NR*DD];    // [B,H,T,HD]
__device__ float g_ao[NR*DD];   // attention out, [B,T,D]

// ---------------------------------------------------------------------------
// LayerNorm: one block per row (1024 floats), 256 threads x float4
// ---------------------------------------------------------------------------
__global__ void ln_kernel(const float* __restrict__ x,
                          const float* __restrict__ gamma,
                          const float* __restrict__ beta) {
    int row = blockIdx.x;
    int t = threadIdx.x;
    const float4* xr = (const float4*)(x + (size_t)row * DD);
    float4 v = xr[t];
    float s  = v.x + v.y + v.z + v.w;
    float sq = v.x*v.x + v.y*v.y + v.z*v.z + v.w*v.w;

    __shared__ float red0[8], red1[8];
    #pragma unroll
    for (int o = 16; o > 0; o >>= 1) {
        s  += __shfl_xor_sync(0xffffffffu, s,  o);
        sq += __shfl_xor_sync(0xffffffffu, sq, o);
    }
    int w = t >> 5, l = t & 31;
    if (l == 0) { red0[w] = s; red1[w] = sq; }
    __syncthreads();
    __shared__ float smu, srs;
    if (t < 32) {
        float a  = (t < 8) ? red0[t] : 0.f;
        float b2 = (t < 8) ? red1[t] : 0.f;
        #pragma unroll
        for (int o = 4; o > 0; o >>= 1) {
            a  += __shfl_xor_sync(0xffffffffu, a,  o);
            b2 += __shfl_xor_sync(0xffffffffu, b2, o);
        }
        if (t == 0) {
            float mu = a * (1.0f / DD);
            float var = b2 * (1.0f / DD) - mu * mu;
            smu = mu;
            srs = rsqrtf(var + 1e-5f);
        }
    }
    __syncthreads();
    float mu = smu, rs = srs;
    float4 gv = ((const float4*)gamma)[t];
    float4 bv = ((const float4*)beta)[t];
    float4 o;
    o.x = (v.x - mu) * rs * gv.x + bv.x;
    o.y = (v.y - mu) * rs * gv.y + bv.y;
    o.z = (v.z - mu) * rs * gv.z + bv.z;
    o.w = (v.w - mu) * rs * gv.w + bv.w;
    ((float4*)(g_xn + (size_t)row * DD))[t] = o;
}

// ---------------------------------------------------------------------------
// QKV GEMM: Y = xn @ W^T + b, written to [B,H,T,HD] layout.
// Tile 64x64x16, block (16,16), 4x4 micro-tile per thread.
// blockIdx.z selects Q/K/V.
// ---------------------------------------------------------------------------
__global__ void qkv_gemm(const float* __restrict__ Wq, const float* __restrict__ bq,
                         const float* __restrict__ Wk, const float* __restrict__ bk,
                         const float* __restrict__ Wv, const float* __restrict__ bv) {
    const float* W; const float* bias; float* dst;
    if (blockIdx.z == 0)      { W = Wq; bias = bq; dst = g_q; }
    else if (blockIdx.z == 1) { W = Wk; bias = bk; dst = g_k; }
    else                      { W = Wv; bias = bv; dst = g_v; }

    int m0 = blockIdx.y * 64;
    int n0 = blockIdx.x * 64;
    int tx = threadIdx.x, ty = threadIdx.y;
    int tid = ty * 16 + tx;

    __shared__ float As[16][68];  // [k][m], padded
    __shared__ float Bs[16][68];  // [k][n], padded

    float acc[4][4] = {};

    int lr = tid >> 2;        // 0..63: tile row
    int lc = (tid & 3) * 4;   // 0,4,8,12: k offset

    const float* Arow = g_xn + (size_t)(m0 + lr) * DD + lc;
    const float* Brow = W    + (size_t)(n0 + lr) * DD + lc;

    for (int k0 = 0; k0 < DD; k0 += 16) {
        float4 a = *(const float4*)(Arow + k0);
        float4 b = *(const float4*)(Brow + k0);
        As[lc+0][lr] = a.x; As[lc+1][lr] = a.y; As[lc+2][lr] = a.z; As[lc+3][lr] = a.w;
        Bs[lc+0][lr] = b.x; Bs[lc+1][lr] = b.y; Bs[lc+2][lr] = b.z; Bs[lc+3][lr] = b.w;
        __syncthreads();
        #pragma unroll
        for (int kk = 0; kk < 16; kk++) {
            float4 av = *(const float4*)&As[kk][ty * 4];
            float4 bvv = *(const float4*)&Bs[kk][tx * 4];
            float af[4] = {av.x, av.y, av.z, av.w};
            float bf[4] = {bvv.x, bvv.y, bvv.z, bvv.w};
            #pragma unroll
            for (int i = 0; i < 4; i++)
                #pragma unroll
                for (int j = 0; j < 4; j++)
                    acc[i][j] += af[i] * bf[j];
        }
        __syncthreads();
    }

    int h = n0 / HD;
    #pragma unroll
    for (int i = 0; i < 4; i++) {
        int r = m0 + ty * 4 + i;
        int b = r >> 11;        // / TT
        int t = r & (TT - 1);
        float* drow = dst + (((size_t)(b * HH + h)) * TT + t) * HD + tx * 4;
        #pragma unroll
        for (int j = 0; j < 4; j++)
            drow[j] = acc[i][j] + bias[n0 + tx * 4 + j];
    }
}

// ---------------------------------------------------------------------------
// Flash attention (causal): block = (q-tile 64, b*h). 64x64 tiles, hd=64.
// smem: Qt [d][q], KP [d][k] (reused as P^T [k][q]), Vs [k][d] = 48KB exactly.
// ---------------------------------------------------------------------------
__global__ void attn_kernel() {
    int qt = blockIdx.x;          // 0..31
    int bh = blockIdx.y;          // 0..63
    const float* Q = g_q + (size_t)bh * TT * HD;
    const float* K = g_k + (size_t)bh * TT * HD;
    const float* V = g_v + (size_t)bh * TT * HD;

    __shared__ float Qt_s[64][64];   // [d][q]
    __shared__ float KP[64][64];     // Kt [d][k] -> then Pt [k][q]
    __shared__ float Vs[64][64];     // [k][d]

    int tx = threadIdx.x, ty = threadIdx.y;
    int tid = ty * 16 + tx;
    int q0 = qt * 64;

    // load Q transposed
    for (int idx = tid; idx < 64 * 16; idx += 256) {
        int r = idx >> 4;
        int c4 = (idx & 15) * 4;
        float4 a = *(const float4*)(Q + (size_t)(q0 + r) * HD + c4);
        Qt_s[c4+0][r] = a.x; Qt_s[c4+1][r] = a.y; Qt_s[c4+2][r] = a.z; Qt_s[c4+3][r] = a.w;
    }

    float m[4], l[4], o[4][4] = {};
    #pragma unroll
    for (int i = 0; i < 4; i++) { m[i] = -1e30f; l[i] = 0.f; }
    __syncthreads();

    for (int kt = 0; kt <= qt; kt++) {
        int k0 = kt * 64;
        // load K transposed, V natural
        for (int idx = tid; idx < 64 * 16; idx += 256) {
            int r = idx >> 4;
            int c4 = (idx & 15) * 4;
            float4 a = *(const float4*)(K + (size_t)(k0 + r) * HD + c4);
            KP[c4+0][r] = a.x; KP[c4+1][r] = a.y; KP[c4+2][r] = a.z; KP[c4+3][r] = a.w;
            float4 b = *(const float4*)(V + (size_t)(k0 + r) * HD + c4);
            *(float4*)&Vs[r][c4] = b;
        }
        __syncthreads();

        // S = Q K^T (reduce over d)
        float s[4][4] = {};
        #pragma unroll
        for (int d = 0; d < 64; d++) {
            float4 qa = *(const float4*)&Qt_s[d][ty * 4];
            float4 kb = *(const float4*)&KP[d][tx * 4];
            float qf[4] = {qa.x, qa.y, qa.z, qa.w};
            float kf[4] = {kb.x, kb.y, kb.z, kb.w};
            #pragma unroll
            for (int i = 0; i < 4; i++)
                #pragma unroll
                for (int j = 0; j < 4; j++)
                    s[i][j] += qf[i] * kf[j];
        }

        const float sc = 0.125f;   // 1/sqrt(64)
        if (kt == qt) {
            #pragma unroll
            for (int i = 0; i < 4; i++) {
                int qg = q0 + ty * 4 + i;
                #pragma unroll
                for (int j = 0; j < 4; j++) {
                    int kg = k0 + tx * 4 + j;
                    s[i][j] = (kg > qg) ? -1e9f : s[i][j] * sc;
                }
            }
        } else {
            #pragma unroll
            for (int i = 0; i < 4; i++)
                #pragma unroll
                for (int j = 0; j < 4; j++)
                    s[i][j] *= sc;
        }

        // online softmax (row groups = 16 lanes sharing ty)
        #pragma unroll
        for (int i = 0; i < 4; i++) {
            float mx = fmaxf(fmaxf(s[i][0], s[i][1]), fmaxf(s[i][2], s[i][3]));
            #pragma unroll
            for (int off = 8; off > 0; off >>= 1)
                mx = fmaxf(mx, __shfl_xor_sync(0xffffffffu, mx, off));
            float mn = fmaxf(m[i], mx);
            float corr = __expf(m[i] - mn);
            l[i] *= corr;
            #pragma unroll
            for (int j = 0; j < 4; j++) o[i][j] *= corr;
            m[i] = mn;
            float rs = 0.f;
            #pragma unroll
            for (int j = 0; j < 4; j++) {
                float p = __expf(s[i][j] - mn);
                s[i][j] = p;
                rs += p;
            }
            #pragma unroll
            for (int off = 8; off > 0; off >>= 1)
                rs += __shfl_xor_sync(0xffffffffu, rs, off);
            l[i] += rs;
        }

        __syncthreads();   // everyone done reading KP as Kt
        // write P^T: KP[k][q]
        #pragma unroll
        for (int i = 0; i < 4; i++)
            #pragma unroll
            for (int j = 0; j < 4; j++)
                KP[tx * 4 + j][ty * 4 + i] = s[i][j];
        __syncthreads();

        // O += P V (reduce over k)
        #pragma unroll
        for (int j = 0; j < 64; j++) {
            float4 pa = *(const float4*)&KP[j][ty * 4];
            float4 vb = *(const float4*)&Vs[j][tx * 4];
            float pf[4] = {pa.x, pa.y, pa.z, pa.w};
            float vf[4] = {vb.x, vb.y, vb.z, vb.w};
            #pragma unroll
            for (int i = 0; i < 4; i++)
                #pragma unroll
                for (int c = 0; c < 4; c++)
                    o[i][c] += pf[i] * vf[c];
        }
        __syncthreads();   // before next tile overwrites KP/Vs
    }

    int b = bh / HH;
    int h = bh % HH;
    #pragma unroll
    for (int i = 0; i < 4; i++) {
        float inv = 1.0f / l[i];
        int qg = q0 + ty * 4 + i;
        float* dst = g_ao + ((size_t)(b * TT + qg)) * DD + h * HD + tx * 4;
        #pragma unroll
        for (int j = 0; j < 4; j++)
            dst[j] = o[i][j] * inv;
    }
}

// ---------------------------------------------------------------------------
// Output projection + residual: out = x + ao @ Wo^T + bo
// ---------------------------------------------------------------------------
__global__ void out_gemm(const float* __restrict__ x,
                         const float* __restrict__ Wo,
                         const float* __restrict__ bo,
                         float* __restrict__ out) {
    int m0 = blockIdx.y * 64;
    int n0 = blockIdx.x * 64;
    int tx = threadIdx.x, ty = threadIdx.y;
    int tid = ty * 16 + tx;

    __shared__ float As[16][68];
    __shared__ float Bs[16][68];

    float acc[4][4] = {};

    int lr = tid >> 2;
    int lc = (tid & 3) * 4;

    const float* Arow = g_ao + (size_t)(m0 + lr) * DD + lc;
    const float* Brow = Wo   + (size_t)(n0 + lr) * DD + lc;

    for (int k0 = 0; k0 < DD; k0 += 16) {
        float4 a = *(const float4*)(Arow + k0);
        float4 b = *(const float4*)(Brow + k0);
        As[lc+0][lr] = a.x; As[lc+1][lr] = a.y; As[lc+2][lr] = a.z; As[lc+3][lr] = a.w;
        Bs[lc+0][lr] = b.x; Bs[lc+1][lr] = b.y; Bs[lc+2][lr] = b.z; Bs[lc+3][lr] = b.w;
        __syncthreads();
        #pragma unroll
        for (int kk = 0; kk < 16; kk++) {
            float4 av = *(const float4*)&As[kk][ty * 4];
            float4 bvv = *(const float4*)&Bs[kk][tx * 4];
            float af[4] = {av.x, av.y, av.z, av.w};
            float bf[4] = {bvv.x, bvv.y, bvv.z, bvv.w};
            #pragma unroll
            for (int i = 0; i < 4; i++)
                #pragma unroll
                for (int j = 0; j < 4; j++)
                    acc[i][j] += af[i] * bf[j];
        }
        __syncthreads();
    }

    #pragma unroll
    for (int i = 0; i < 4; i++) {
        int r = m0 + ty * 4 + i;
        const float* xr = x + (size_t)r * DD + n0 + tx * 4;
        float* orow = out + (size_t)r * DD + n0 + tx * 4;
        #pragma unroll
        for (int j = 0; j < 4; j++)
            orow[j] = acc[i][j] + bo[n0 + tx * 4 + j] + xr[j];
    }
}

// ---------------------------------------------------------------------------
extern "C" void kernel_launch(void* const* d_in, const int* in_sizes, int n_in,
                              void* d_out, int out_size) {
    const float* x     = (const float*)d_in[0];
    const float* Wq    = (const float*)d_in[1];
    const float* bq    = (const float*)d_in[2];
    const float* Wk    = (const float*)d_in[3];
    const float* bk    = (const float*)d_in[4];
    const float* Wv    = (const float*)d_in[5];
    const float* bv    = (const float*)d_in[6];
    const float* Wo    = (const float*)d_in[7];
    const float* bo    = (const float*)d_in[8];
    const float* gamma = (const float*)d_in[9];
    const float* beta  = (const float*)d_in[10];
    float* out = (float*)d_out;

    ln_kernel<<<NR, 256>>>(x, gamma, beta);

    dim3 blk(16, 16);
    dim3 grid_qkv(DD / 64, NR / 64, 3);
    qkv_gemm<<<grid_qkv, blk>>>(Wq, bq, Wk, bk, Wv, bv);

    dim3 grid_attn(TT / 64, BB * HH);
    attn_kernel<<<grid_attn, blk>>>();

    dim3 grid_out(DD / 64, NR / 64);
    out_gemm<<<grid_out, blk>>>(x, Wo, bo, out);
}

// round 3
// speedup vs baseline: 1.4820x; 1.4820x over previous
#include <cuda_runtime.h>
#include <cuda_bf16.h>
#include <cstdint>

#define BB 4
#define TT 2048
#define DD 1024
#define HH 16
#define HD 64
#define NR (BB*TT)   // 8192

// ---------------- device scratch (allocation-free rule) ----------------
__device__ float g_q[NR*DD];                 // [B,H,T,HD] fp32
__device__ float g_k[NR*DD];
__device__ float g_v[NR*DD];
__device__ __nv_bfloat16 g_xnh[NR*DD];       // layernormed x, bf16 hi
__device__ __nv_bfloat16 g_xnl[NR*DD];       // bf16 lo residual
__device__ __nv_bfloat16 g_aoh[NR*DD];       // attention out hi  [B*T, D]
__device__ __nv_bfloat16 g_aol[NR*DD];
__device__ __nv_bfloat16 g_wh[4u*DD*DD];     // Wq,Wk,Wv,Wo hi
__device__ __nv_bfloat16 g_wl[4u*DD*DD];     // lo

__device__ __forceinline__ uint32_t smem_u32(const void* p) {
    uint32_t a;
    asm("{ .reg .u64 t; cvta.to.shared.u64 t, %1; cvt.u32.u64 %0, t; }" : "=r"(a) : "l"(p));
    return a;
}

__device__ __forceinline__ void split_bf16(float v, __nv_bfloat16& h, __nv_bfloat16& l) {
    h = __float2bfloat16(v);
    l = __float2bfloat16(v - __bfloat162float(h));
}

// mma.m16n8k16 bf16 helpers
__device__ __forceinline__ void mma16816(float (&c)[4], const uint32_t (&a)[4],
                                         uint32_t b0, uint32_t b1) {
    asm volatile(
        "mma.sync.aligned.m16n8k16.row.col.f32.bf16.bf16.f32 "
        "{%0,%1,%2,%3},{%4,%5,%6,%7},{%8,%9},{%0,%1,%2,%3};"
        : "+f"(c[0]), "+f"(c[1]), "+f"(c[2]), "+f"(c[3])
        : "r"(a[0]), "r"(a[1]), "r"(a[2]), "r"(a[3]), "r"(b0), "r"(b1));
}
__device__ __forceinline__ void ldm_x4(uint32_t (&r)[4], uint32_t addr) {
    asm volatile("ldmatrix.sync.aligned.m8n8.x4.shared.b16 {%0,%1,%2,%3}, [%4];"
                 : "=r"(r[0]), "=r"(r[1]), "=r"(r[2]), "=r"(r[3]) : "r"(addr));
}

// ---------------------------------------------------------------------------
// Weight split: fp32 -> bf16 hi/lo for Wq,Wk,Wv,Wo
// ---------------------------------------------------------------------------
__global__ void wconv_kernel(const float* __restrict__ Wq, const float* __restrict__ Wk,
                             const float* __restrict__ Wv, const float* __restrict__ Wo) {
    int m = blockIdx.y;
    const float* W = (m == 0) ? Wq : (m == 1) ? Wk : (m == 2) ? Wv : Wo;
    size_t base = (size_t)m * DD * DD;
    int idx = blockIdx.x * 256 + threadIdx.x;
    float4 v = ((const float4*)W)[idx];
    __nv_bfloat16 h0, h1, h2, h3, l0, l1, l2, l3;
    split_bf16(v.x, h0, l0); split_bf16(v.y, h1, l1);
    split_bf16(v.z, h2, l2); split_bf16(v.w, h3, l3);
    __nv_bfloat162* dh = (__nv_bfloat162*)(g_wh + base + (size_t)idx * 4);
    __nv_bfloat162* dl = (__nv_bfloat162*)(g_wl + base + (size_t)idx * 4);
    dh[0] = __nv_bfloat162{h0, h1}; dh[1] = __nv_bfloat162{h2, h3};
    dl[0] = __nv_bfloat162{l0, l1}; dl[1] = __nv_bfloat162{l2, l3};
}

// ---------------------------------------------------------------------------
// LayerNorm -> bf16 hi/lo
// ---------------------------------------------------------------------------
__global__ void ln_kernel(const float* __restrict__ x,
                          const float* __restrict__ gamma,
                          const float* __restrict__ beta) {
    int row = blockIdx.x;
    int t = threadIdx.x;
    const float4* xr = (const float4*)(x + (size_t)row * DD);
    float4 v = xr[t];
    float s  = v.x + v.y + v.z + v.w;
    float sq = v.x*v.x + v.y*v.y + v.z*v.z + v.w*v.w;

    __shared__ float red0[8], red1[8];
    #pragma unroll
    for (int o = 16; o > 0; o >>= 1) {
        s  += __shfl_xor_sync(0xffffffffu, s,  o);
        sq += __shfl_xor_sync(0xffffffffu, sq, o);
    }
    int w = t >> 5, l = t & 31;
    if (l == 0) { red0[w] = s; red1[w] = sq; }
    __syncthreads();
    __shared__ float smu, srs;
    if (t < 32) {
        float a  = (t < 8) ? red0[t] : 0.f;
        float b2 = (t < 8) ? red1[t] : 0.f;
        #pragma unroll
        for (int o = 4; o > 0; o >>= 1) {
            a  += __shfl_xor_sync(0xffffffffu, a,  o);
            b2 += __shfl_xor_sync(0xffffffffu, b2, o);
        }
        if (t == 0) {
            float mu = a * (1.0f / DD);
            float var = b2 * (1.0f / DD) - mu * mu;
            smu = mu; srs = rsqrtf(var + 1e-5f);
        }
    }
    __syncthreads();
    float mu = smu, rs = srs;
    float4 gv = ((const float4*)gamma)[t];
    float4 bv = ((const float4*)beta)[t];
    float o0 = (v.x - mu) * rs * gv.x + bv.x;
    float o1 = (v.y - mu) * rs * gv.y + bv.y;
    float o2 = (v.z - mu) * rs * gv.z + bv.z;
    float o3 = (v.w - mu) * rs * gv.w + bv.w;
    __nv_bfloat16 h0,h1,h2,h3,l0,l1,l2,l3;
    split_bf16(o0,h0,l0); split_bf16(o1,h1,l1); split_bf16(o2,h2,l2); split_bf16(o3,h3,l3);
    size_t off = (size_t)row * DD + t * 4;
    ((__nv_bfloat162*)(g_xnh + off))[0] = __nv_bfloat162{h0,h1};
    ((__nv_bfloat162*)(g_xnh + off))[1] = __nv_bfloat162{h2,h3};
    ((__nv_bfloat162*)(g_xnl + off))[0] = __nv_bfloat162{l0,l1};
    ((__nv_bfloat162*)(g_xnl + off))[1] = __nv_bfloat162{l2,l3};
}

// ---------------------------------------------------------------------------
// Tensor-core GEMM core (shared by qkv and out kernels).
// 128x128 tile, k-chunk 32, 8 warps as 4(m) x 2(n).
// Computes acc = (Ah+Al) @ (Bh+Bl)^T via 3 mmas (AhBh + AhBl + AlBh).
// Smem: rows padded to 40 bf16 for conflict-free ldmatrix.
// ---------------------------------------------------------------------------
#define SPITCH 40

struct GemmSmem {
    __nv_bfloat16 Ah[128 * SPITCH];
    __nv_bfloat16 Al[128 * SPITCH];
    __nv_bfloat16 Bh[128 * SPITCH];
    __nv_bfloat16 Bl[128 * SPITCH];
};

__device__ __forceinline__ void gemm_core(
    const __nv_bfloat16* __restrict__ Ahg, const __nv_bfloat16* __restrict__ Alg,
    const __nv_bfloat16* __restrict__ Bhg, const __nv_bfloat16* __restrict__ Blg,
    GemmSmem& sm, float (&acc)[2][8][4], int tid)
{
    int lane = tid & 31;
    int w = tid >> 5;
    int wm = w & 3;        // m offset = wm*32
    int wn = w >> 2;       // n offset = wn*64

    uint32_t Ah_u = smem_u32(sm.Ah);
    uint32_t Al_u = smem_u32(sm.Al);
    uint32_t Bh_u = smem_u32(sm.Bh);
    uint32_t Bl_u = smem_u32(sm.Bl);

    // ldmatrix lane addressing
    int a_row = (lane & 15), a_cg = (lane >> 4) * 8;             // A: x4 over 16x16
    int quad = lane >> 3;
    int b_row = (lane & 7) + ((quad & 2) ? 8 : 0);               // B: x4 over 16(n)x16(k)
    int b_col = (quad & 1) ? 8 : 0;

    for (int kc = 0; kc < DD / 32; kc++) {
        // ---- load A/B chunk to smem (each thread: 2 x uint4 per matrix) ----
        #pragma unroll
        for (int u = 0; u < 2; u++) {
            int idx = tid * 2 + u;          // 0..511
            int row = idx >> 2;
            int seg = (idx & 3) * 8;
            size_t g = (size_t)row * DD + kc * 32 + seg;
            uint32_t so = (uint32_t)(row * SPITCH + seg);
            *(uint4*)(sm.Ah + so) = *(const uint4*)(Ahg + g);
            *(uint4*)(sm.Al + so) = *(const uint4*)(Alg + g);
            *(uint4*)(sm.Bh + so) = *(const uint4*)(Bhg + g);
            *(uint4*)(sm.Bl + so) = *(const uint4*)(Blg + g);
        }
        __syncthreads();

        #pragma unroll
        for (int s = 0; s < 2; s++) {       // k-step of 16
            uint32_t ah[2][4], al[2][4];
            #pragma unroll
            for (int mt = 0; mt < 2; mt++) {
                uint32_t off = (uint32_t)((wm * 32 + mt * 16 + a_row) * SPITCH + s * 16 + a_cg) * 2;
                ldm_x4(ah[mt], Ah_u + off);
                ldm_x4(al[mt], Al_u + off);
            }
            #pragma unroll
            for (int nt2 = 0; nt2 < 4; nt2++) {   // pairs of n-tiles
                uint32_t boff = (uint32_t)((wn * 64 + nt2 * 16 + b_row) * SPITCH + s * 16 + b_col) * 2;
                uint32_t bh[4], bl[4];
                ldm_x4(bh, Bh_u + boff);
                ldm_x4(bl, Bl_u + boff);
                #pragma unroll
                for (int half = 0; half < 2; half++) {
                    int nt = nt2 * 2 + half;
                    uint32_t bh0 = bh[half*2], bh1 = bh[half*2+1];
                    uint32_t bl0 = bl[half*2], bl1 = bl[half*2+1];
                    #pragma unroll
                    for (int mt = 0; mt < 2; mt++) {
                        mma16816(acc[mt][nt], ah[mt], bh0, bh1);
                        mma16816(acc[mt][nt], ah[mt], bl0, bl1);
                        mma16816(acc[mt][nt], al[mt], bh0, bh1);
                    }
                }
            }
        }
        __syncthreads();
    }
}

// ---------------------------------------------------------------------------
// QKV projection: Y = xn @ W^T + b -> [B,H,T,HD] fp32. z selects Q/K/V.
// ---------------------------------------------------------------------------
__global__ void __launch_bounds__(256, 2) qkv_mma_kernel(
    const float* __restrict__ bq, const float* __restrict__ bk, const float* __restrict__ bv)
{
    __shared__ GemmSmem sm;
    int tid = threadIdx.x;
    int z = blockIdx.z;
    int m0 = blockIdx.y * 128;
    int n0 = blockIdx.x * 128;

    const float* bias; float* dst;
    if (z == 0)      { bias = bq; dst = g_q; }
    else if (z == 1) { bias = bk; dst = g_k; }
    else             { bias = bv; dst = g_v; }

    float acc[2][8][4] = {};
    gemm_core(g_xnh + (size_t)m0 * DD, g_xnl + (size_t)m0 * DD,
              g_wh + (size_t)z * DD * DD + (size_t)n0 * DD,
              g_wl + (size_t)z * DD * DD + (size_t)n0 * DD,
              sm, acc, tid);

    int lane = tid & 31;
    int w = tid >> 5, wm = w & 3, wn = w >> 2;
    #pragma unroll
    for (int mt = 0; mt < 2; mt++) {
        #pragma unroll
        for (int nt = 0; nt < 8; nt++) {
            int r = m0 + wm * 32 + mt * 16 + (lane >> 2);
            int c = n0 + wn * 64 + nt * 8 + (lane & 3) * 2;
            float b0 = bias[c], b1 = bias[c + 1];
            #pragma unroll
            for (int rr = 0; rr < 2; rr++) {
                int row = r + rr * 8;
                int b = row >> 11, t = row & (TT - 1);
                int h = c >> 6, hd = c & 63;
                float* p = dst + (((size_t)(b * HH + h)) * TT + t) * HD + hd;
                float2 v;
                v.x = acc[mt][nt][rr * 2 + 0] + b0;
                v.y = acc[mt][nt][rr * 2 + 1] + b1;
                *(float2*)p = v;
            }
        }
    }
}

// ---------------------------------------------------------------------------
// Output projection: out = x + ao @ Wo^T + bo
// ---------------------------------------------------------------------------
__global__ void __launch_bounds__(256, 2) out_mma_kernel(
    const float* __restrict__ x, const float* __restrict__ bo, float* __restrict__ out)
{
    __shared__ GemmSmem sm;
    int tid = threadIdx.x;
    int m0 = blockIdx.y * 128;
    int n0 = blockIdx.x * 128;

    float acc[2][8][4] = {};
    gemm_core(g_aoh + (size_t)m0 * DD, g_aol + (size_t)m0 * DD,
              g_wh + (size_t)3 * DD * DD + (size_t)n0 * DD,
              g_wl + (size_t)3 * DD * DD + (size_t)n0 * DD,
              sm, acc, tid);

    int lane = tid & 31;
    int w = tid >> 5, wm = w & 3, wn = w >> 2;
    #pragma unroll
    for (int mt = 0; mt < 2; mt++) {
        #pragma unroll
        for (int nt = 0; nt < 8; nt++) {
            int r = m0 + wm * 32 + mt * 16 + (lane >> 2);
            int c = n0 + wn * 64 + nt * 8 + (lane & 3) * 2;
            float b0 = bo[c], b1 = bo[c + 1];
            #pragma unroll
            for (int rr = 0; rr < 2; rr++) {
                int row = r + rr * 8;
                const float* xp = x + (size_t)row * DD + c;
                float* p = out + (size_t)row * DD + c;
                float2 xv = *(const float2*)xp;
                float2 v;
                v.x = acc[mt][nt][rr * 2 + 0] + b0 + xv.x;
                v.y = acc[mt][nt][rr * 2 + 1] + b1 + xv.y;
                *(float2*)p = v;
            }
        }
    }
}

// ---------------------------------------------------------------------------
// Flash attention (causal), fp32 FFMA; epilogue emits bf16 hi/lo
// ---------------------------------------------------------------------------
__global__ void attn_kernel() {
    int qt = blockIdx.x;
    int bh = blockIdx.y;
    const float* Q = g_q + (size_t)bh * TT * HD;
    const float* K = g_k + (size_t)bh * TT * HD;
    const float* V = g_v + (size_t)bh * TT * HD;

    __shared__ float Qt_s[64][64];
    __shared__ float KP[64][64];
    __shared__ float Vs[64][64];

    int tx = threadIdx.x, ty = threadIdx.y;
    int tid = ty * 16 + tx;
    int q0 = qt * 64;

    for (int idx = tid; idx < 64 * 16; idx += 256) {
        int r = idx >> 4;
        int c4 = (idx & 15) * 4;
        float4 a = *(const float4*)(Q + (size_t)(q0 + r) * HD + c4);
        Qt_s[c4+0][r] = a.x; Qt_s[c4+1][r] = a.y; Qt_s[c4+2][r] = a.z; Qt_s[c4+3][r] = a.w;
    }

    float m[4], l[4], o[4][4] = {};
    #pragma unroll
    for (int i = 0; i < 4; i++) { m[i] = -1e30f; l[i] = 0.f; }
    __syncthreads();

    for (int kt = 0; kt <= qt; kt++) {
        int k0 = kt * 64;
        for (int idx = tid; idx < 64 * 16; idx += 256) {
            int r = idx >> 4;
            int c4 = (idx & 15) * 4;
            float4 a = *(const float4*)(K + (size_t)(k0 + r) * HD + c4);
            KP[c4+0][r] = a.x; KP[c4+1][r] = a.y; KP[c4+2][r] = a.z; KP[c4+3][r] = a.w;
            float4 b = *(const float4*)(V + (size_t)(k0 + r) * HD + c4);
            *(float4*)&Vs[r][c4] = b;
        }
        __syncthreads();

        float s[4][4] = {};
        #pragma unroll
        for (int d = 0; d < 64; d++) {
            float4 qa = *(const float4*)&Qt_s[d][ty * 4];
            float4 kb = *(const float4*)&KP[d][tx * 4];
            float qf[4] = {qa.x, qa.y, qa.z, qa.w};
            float kf[4] = {kb.x, kb.y, kb.z, kb.w};
            #pragma unroll
            for (int i = 0; i < 4; i++)
                #pragma unroll
                for (int j = 0; j < 4; j++)
                    s[i][j] += qf[i] * kf[j];
        }

        const float sc = 0.125f;
        if (kt == qt) {
            #pragma unroll
            for (int i = 0; i < 4; i++) {
                int qg = q0 + ty * 4 + i;
                #pragma unroll
                for (int j = 0; j < 4; j++) {
                    int kg = k0 + tx * 4 + j;
                    s[i][j] = (kg > qg) ? -1e9f : s[i][j] * sc;
                }
            }
        } else {
            #pragma unroll
            for (int i = 0; i < 4; i++)
                #pragma unroll
                for (int j = 0; j < 4; j++)
                    s[i][j] *= sc;
        }

        #pragma unroll
        for (int i = 0; i < 4; i++) {
            float mx = fmaxf(fmaxf(s[i][0], s[i][1]), fmaxf(s[i][2], s[i][3]));
            #pragma unroll
            for (int off = 8; off > 0; off >>= 1)
                mx = fmaxf(mx, __shfl_xor_sync(0xffffffffu, mx, off));
            float mn = fmaxf(m[i], mx);
            float corr = __expf(m[i] - mn);
            l[i] *= corr;
            #pragma unroll
            for (int j = 0; j < 4; j++) o[i][j] *= corr;
            m[i] = mn;
            float rs = 0.f;
            #pragma unroll
            for (int j = 0; j < 4; j++) {
                float p = __expf(s[i][j] - mn);
                s[i][j] = p;
                rs += p;
            }
            #pragma unroll
            for (int off = 8; off > 0; off >>= 1)
                rs += __shfl_xor_sync(0xffffffffu, rs, off);
            l[i] += rs;
        }

        __syncthreads();
        #pragma unroll
        for (int i = 0; i < 4; i++)
            #pragma unroll
            for (int j = 0; j < 4; j++)
                KP[tx * 4 + j][ty * 4 + i] = s[i][j];
        __syncthreads();

        #pragma unroll
        for (int j = 0; j < 64; j++) {
            float4 pa = *(const float4*)&KP[j][ty * 4];
            float4 vb = *(const float4*)&Vs[j][tx * 4];
            float pf[4] = {pa.x, pa.y, pa.z, pa.w};
            float vf[4] = {vb.x, vb.y, vb.z, vb.w};
            #pragma unroll
            for (int i = 0; i < 4; i++)
                #pragma unroll
                for (int c = 0; c < 4; c++)
                    o[i][c] += pf[i] * vf[c];
        }
        __syncthreads();
    }

    int b = bh / HH;
    int h = bh % HH;
    #pragma unroll
    for (int i = 0; i < 4; i++) {
        float inv = 1.0f / l[i];
        int qg = q0 + ty * 4 + i;
        size_t off = ((size_t)(b * TT + qg)) * DD + h * HD + tx * 4;
        float v0 = o[i][0] * inv, v1 = o[i][1] * inv, v2 = o[i][2] * inv, v3 = o[i][3] * inv;
        __nv_bfloat16 h0,h1,h2,h3,l0,l1,l2,l3;
        split_bf16(v0,h0,l0); split_bf16(v1,h1,l1); split_bf16(v2,h2,l2); split_bf16(v3,h3,l3);
        ((__nv_bfloat162*)(g_aoh + off))[0] = __nv_bfloat162{h0,h1};
        ((__nv_bfloat162*)(g_aoh + off))[1] = __nv_bfloat162{h2,h3};
        ((__nv_bfloat162*)(g_aol + off))[0] = __nv_bfloat162{l0,l1};
        ((__nv_bfloat162*)(g_aol + off))[1] = __nv_bfloat162{l2,l3};
    }
}

// ---------------------------------------------------------------------------
extern "C" void kernel_launch(void* const* d_in, const int* in_sizes, int n_in,
                              void* d_out, int out_size) {
    const float* x     = (const float*)d_in[0];
    const float* bq    = (const float*)d_in[2];
    const float* bk    = (const float*)d_in[4];
    const float* bv    = (const float*)d_in[6];
    const float* bo    = (const float*)d_in[8];
    const float* gamma = (const float*)d_in[9];
    const float* beta  = (const float*)d_in[10];
    float* out = (float*)d_out;

    ln_kernel<<<NR, 256>>>(x, gamma, beta);

    dim3 wgrid(1024, 4);
    wconv_kernel<<<wgrid, 256>>>((const float*)d_in[1], (const float*)d_in[3],
                                 (const float*)d_in[5], (const float*)d_in[7]);

    dim3 grid_qkv(DD / 128, NR / 128, 3);
    qkv_mma_kernel<<<grid_qkv, 256>>>(bq, bk, bv);

    dim3 blk(16, 16);
    dim3 grid_attn(TT / 64, BB * HH);
    attn_kernel<<<grid_attn, blk>>>();

    dim3 grid_out(DD / 128, NR / 128);
    out_mma_kernel<<<grid_out, 256>>>(x, bo, out);
}

// round 4
// speedup vs baseline: 3.3168x; 2.2381x over previous
#include <cuda_runtime.h>
#include <cuda_bf16.h>
#include <cstdint>

#define BB 4
#define TT 2048
#define DD 1024
#define HH 16
#define HD 64
#define NR (BB*TT)   // 8192

// ---------------- device scratch (allocation-free rule) ----------------
__device__ __nv_bfloat16 g_qb[NR*DD];        // [B,H,T,HD] bf16 (q pre-scaled by 0.125)
__device__ __nv_bfloat16 g_kb[NR*DD];
__device__ __nv_bfloat16 g_vb[NR*DD];
__device__ __nv_bfloat16 g_xnh[NR*DD];       // layernormed x, bf16 hi
__device__ __nv_bfloat16 g_xnl[NR*DD];       // bf16 lo residual
__device__ __nv_bfloat16 g_aoh[NR*DD];       // attention out hi  [B*T, D]
__device__ __nv_bfloat16 g_aol[NR*DD];
__device__ __nv_bfloat16 g_wh[4u*DD*DD];     // Wq,Wk,Wv,Wo hi
__device__ __nv_bfloat16 g_wl[4u*DD*DD];     // lo

__device__ __forceinline__ uint32_t smem_u32(const void* p) {
    uint32_t a;
    asm("{ .reg .u64 t; cvta.to.shared.u64 t, %1; cvt.u32.u64 %0, t; }" : "=r"(a) : "l"(p));
    return a;
}
__device__ __forceinline__ void split_bf16(float v, __nv_bfloat16& h, __nv_bfloat16& l) {
    h = __float2bfloat16(v);
    l = __float2bfloat16(v - __bfloat162float(h));
}
__device__ __forceinline__ uint32_t packbf(float a, float b) {
    __nv_bfloat162 t = __floats2bfloat162_rn(a, b);
    return *(uint32_t*)&t;
}

// mma.m16n8k16 bf16 helpers
__device__ __forceinline__ void mma16816(float (&c)[4], const uint32_t (&a)[4],
                                         uint32_t b0, uint32_t b1) {
    asm volatile(
        "mma.sync.aligned.m16n8k16.row.col.f32.bf16.bf16.f32 "
        "{%0,%1,%2,%3},{%4,%5,%6,%7},{%8,%9},{%0,%1,%2,%3};"
        : "+f"(c[0]), "+f"(c[1]), "+f"(c[2]), "+f"(c[3])
        : "r"(a[0]), "r"(a[1]), "r"(a[2]), "r"(a[3]), "r"(b0), "r"(b1));
}
__device__ __forceinline__ void ldm_x4(uint32_t (&r)[4], uint32_t addr) {
    asm volatile("ldmatrix.sync.aligned.m8n8.x4.shared.b16 {%0,%1,%2,%3}, [%4];"
                 : "=r"(r[0]), "=r"(r[1]), "=r"(r[2]), "=r"(r[3]) : "r"(addr));
}
__device__ __forceinline__ void ldm_x4_t(uint32_t (&r)[4], uint32_t addr) {
    asm volatile("ldmatrix.sync.aligned.m8n8.x4.trans.shared.b16 {%0,%1,%2,%3}, [%4];"
                 : "=r"(r[0]), "=r"(r[1]), "=r"(r[2]), "=r"(r[3]) : "r"(addr));
}

// ---------------------------------------------------------------------------
// Weight split: fp32 -> bf16 hi/lo for Wq,Wk,Wv,Wo
// ---------------------------------------------------------------------------
__global__ void wconv_kernel(const float* __restrict__ Wq, const float* __restrict__ Wk,
                             const float* __restrict__ Wv, const float* __restrict__ Wo) {
    int m = blockIdx.y;
    const float* W = (m == 0) ? Wq : (m == 1) ? Wk : (m == 2) ? Wv : Wo;
    size_t base = (size_t)m * DD * DD;
    int idx = blockIdx.x * 256 + threadIdx.x;
    float4 v = ((const float4*)W)[idx];
    __nv_bfloat16 h0, h1, h2, h3, l0, l1, l2, l3;
    split_bf16(v.x, h0, l0); split_bf16(v.y, h1, l1);
    split_bf16(v.z, h2, l2); split_bf16(v.w, h3, l3);
    __nv_bfloat162* dh = (__nv_bfloat162*)(g_wh + base + (size_t)idx * 4);
    __nv_bfloat162* dl = (__nv_bfloat162*)(g_wl + base + (size_t)idx * 4);
    dh[0] = __nv_bfloat162{h0, h1}; dh[1] = __nv_bfloat162{h2, h3};
    dl[0] = __nv_bfloat162{l0, l1}; dl[1] = __nv_bfloat162{l2, l3};
}

// ---------------------------------------------------------------------------
// LayerNorm -> bf16 hi/lo
// ---------------------------------------------------------------------------
__global__ void ln_kernel(const float* __restrict__ x,
                          const float* __restrict__ gamma,
                          const float* __restrict__ beta) {
    int row = blockIdx.x;
    int t = threadIdx.x;
    const float4* xr = (const float4*)(x + (size_t)row * DD);
    float4 v = xr[t];
    float s  = v.x + v.y + v.z + v.w;
    float sq = v.x*v.x + v.y*v.y + v.z*v.z + v.w*v.w;

    __shared__ float red0[8], red1[8];
    #pragma unroll
    for (int o = 16; o > 0; o >>= 1) {
        s  += __shfl_xor_sync(0xffffffffu, s,  o);
        sq += __shfl_xor_sync(0xffffffffu, sq, o);
    }
    int w = t >> 5, l = t & 31;
    if (l == 0) { red0[w] = s; red1[w] = sq; }
    __syncthreads();
    __shared__ float smu, srs;
    if (t < 32) {
        float a  = (t < 8) ? red0[t] : 0.f;
        float b2 = (t < 8) ? red1[t] : 0.f;
        #pragma unroll
        for (int o = 4; o > 0; o >>= 1) {
            a  += __shfl_xor_sync(0xffffffffu, a,  o);
            b2 += __shfl_xor_sync(0xffffffffu, b2, o);
        }
        if (t == 0) {
            float mu = a * (1.0f / DD);
            float var = b2 * (1.0f / DD) - mu * mu;
            smu = mu; srs = rsqrtf(var + 1e-5f);
        }
    }
    __syncthreads();
    float mu = smu, rs = srs;
    float4 gv = ((const float4*)gamma)[t];
    float4 bv = ((const float4*)beta)[t];
    float o0 = (v.x - mu) * rs * gv.x + bv.x;
    float o1 = (v.y - mu) * rs * gv.y + bv.y;
    float o2 = (v.z - mu) * rs * gv.z + bv.z;
    float o3 = (v.w - mu) * rs * gv.w + bv.w;
    __nv_bfloat16 h0,h1,h2,h3,l0,l1,l2,l3;
    split_bf16(o0,h0,l0); split_bf16(o1,h1,l1); split_bf16(o2,h2,l2); split_bf16(o3,h3,l3);
    size_t off = (size_t)row * DD + t * 4;
    ((__nv_bfloat162*)(g_xnh + off))[0] = __nv_bfloat162{h0,h1};
    ((__nv_bfloat162*)(g_xnh + off))[1] = __nv_bfloat162{h2,h3};
    ((__nv_bfloat162*)(g_xnl + off))[0] = __nv_bfloat162{l0,l1};
    ((__nv_bfloat162*)(g_xnl + off))[1] = __nv_bfloat162{l2,l3};
}

// ---------------------------------------------------------------------------
// Tensor-core GEMM core. 128x128 tile, k-chunk 32, 8 warps 4(m)x2(n).
// acc = (Ah+Al) @ (Bh+Bl)^T via 3 mmas.
// ---------------------------------------------------------------------------
#define SPITCH 40

struct GemmSmem {
    __nv_bfloat16 Ah[128 * SPITCH];
    __nv_bfloat16 Al[128 * SPITCH];
    __nv_bfloat16 Bh[128 * SPITCH];
    __nv_bfloat16 Bl[128 * SPITCH];
};

__device__ __forceinline__ void gemm_core(
    const __nv_bfloat16* __restrict__ Ahg, const __nv_bfloat16* __restrict__ Alg,
    const __nv_bfloat16* __restrict__ Bhg, const __nv_bfloat16* __restrict__ Blg,
    GemmSmem& sm, float (&acc)[2][8][4], int tid)
{
    int lane = tid & 31;
    int w = tid >> 5;
    int wm = w & 3;
    int wn = w >> 2;

    uint32_t Ah_u = smem_u32(sm.Ah);
    uint32_t Al_u = smem_u32(sm.Al);
    uint32_t Bh_u = smem_u32(sm.Bh);
    uint32_t Bl_u = smem_u32(sm.Bl);

    int a_row = (lane & 15), a_cg = (lane >> 4) * 8;
    int quad = lane >> 3;
    int b_row = (lane & 7) + ((quad & 2) ? 8 : 0);
    int b_col = (quad & 1) ? 8 : 0;

    for (int kc = 0; kc < DD / 32; kc++) {
        #pragma unroll
        for (int u = 0; u < 2; u++) {
            int idx = tid * 2 + u;
            int row = idx >> 2;
            int seg = (idx & 3) * 8;
            size_t g = (size_t)row * DD + kc * 32 + seg;
            uint32_t so = (uint32_t)(row * SPITCH + seg);
            *(uint4*)(sm.Ah + so) = *(const uint4*)(Ahg + g);
            *(uint4*)(sm.Al + so) = *(const uint4*)(Alg + g);
            *(uint4*)(sm.Bh + so) = *(const uint4*)(Bhg + g);
            *(uint4*)(sm.Bl + so) = *(const uint4*)(Blg + g);
        }
        __syncthreads();

        #pragma unroll
        for (int s = 0; s < 2; s++) {
            uint32_t ah[2][4], al[2][4];
            #pragma unroll
            for (int mt = 0; mt < 2; mt++) {
                uint32_t off = (uint32_t)((wm * 32 + mt * 16 + a_row) * SPITCH + s * 16 + a_cg) * 2;
                ldm_x4(ah[mt], Ah_u + off);
                ldm_x4(al[mt], Al_u + off);
            }
            #pragma unroll
            for (int nt2 = 0; nt2 < 4; nt2++) {
                uint32_t boff = (uint32_t)((wn * 64 + nt2 * 16 + b_row) * SPITCH + s * 16 + b_col) * 2;
                uint32_t bh[4], bl[4];
                ldm_x4(bh, Bh_u + boff);
                ldm_x4(bl, Bl_u + boff);
                #pragma unroll
                for (int half = 0; half < 2; half++) {
                    int nt = nt2 * 2 + half;
                    uint32_t bh0 = bh[half*2], bh1 = bh[half*2+1];
                    uint32_t bl0 = bl[half*2], bl1 = bl[half*2+1];
                    #pragma unroll
                    for (int mt = 0; mt < 2; mt++) {
                        mma16816(acc[mt][nt], ah[mt], bh0, bh1);
                        mma16816(acc[mt][nt], ah[mt], bl0, bl1);
                        mma16816(acc[mt][nt], al[mt], bh0, bh1);
                    }
                }
            }
        }
        __syncthreads();
    }
}

// ---------------------------------------------------------------------------
// QKV projection -> bf16 [B,H,T,HD]; q pre-scaled by 0.125
// ---------------------------------------------------------------------------
__global__ void __launch_bounds__(256, 2) qkv_mma_kernel(
    const float* __restrict__ bq, const float* __restrict__ bk, const float* __restrict__ bv)
{
    __shared__ GemmSmem sm;
    int tid = threadIdx.x;
    int z = blockIdx.z;
    int m0 = blockIdx.y * 128;
    int n0 = blockIdx.x * 128;

    const float* bias; __nv_bfloat16* dst; float sc;
    if (z == 0)      { bias = bq; dst = g_qb; sc = 0.125f; }
    else if (z == 1) { bias = bk; dst = g_kb; sc = 1.0f; }
    else             { bias = bv; dst = g_vb; sc = 1.0f; }

    float acc[2][8][4] = {};
    gemm_core(g_xnh + (size_t)m0 * DD, g_xnl + (size_t)m0 * DD,
              g_wh + (size_t)z * DD * DD + (size_t)n0 * DD,
              g_wl + (size_t)z * DD * DD + (size_t)n0 * DD,
              sm, acc, tid);

    int lane = tid & 31;
    int w = tid >> 5, wm = w & 3, wn = w >> 2;
    #pragma unroll
    for (int mt = 0; mt < 2; mt++) {
        #pragma unroll
        for (int nt = 0; nt < 8; nt++) {
            int r = m0 + wm * 32 + mt * 16 + (lane >> 2);
            int c = n0 + wn * 64 + nt * 8 + (lane & 3) * 2;
            float b0 = bias[c], b1 = bias[c + 1];
            #pragma unroll
            for (int rr = 0; rr < 2; rr++) {
                int row = r + rr * 8;
                int b = row >> 11, t = row & (TT - 1);
                int h = c >> 6, hd = c & 63;
                __nv_bfloat16* p = dst + (((size_t)(b * HH + h)) * TT + t) * HD + hd;
                float vx = (acc[mt][nt][rr * 2 + 0] + b0) * sc;
                float vy = (acc[mt][nt][rr * 2 + 1] + b1) * sc;
                *(__nv_bfloat162*)p = __floats2bfloat162_rn(vx, vy);
            }
        }
    }
}

// ---------------------------------------------------------------------------
// Output projection: out = x + ao @ Wo^T + bo
// ---------------------------------------------------------------------------
__global__ void __launch_bounds__(256, 2) out_mma_kernel(
    const float* __restrict__ x, const float* __restrict__ bo, float* __restrict__ out)
{
    __shared__ GemmSmem sm;
    int tid = threadIdx.x;
    int m0 = blockIdx.y * 128;
    int n0 = blockIdx.x * 128;

    float acc[2][8][4] = {};
    gemm_core(g_aoh + (size_t)m0 * DD, g_aol + (size_t)m0 * DD,
              g_wh + (size_t)3 * DD * DD + (size_t)n0 * DD,
              g_wl + (size_t)3 * DD * DD + (size_t)n0 * DD,
              sm, acc, tid);

    int lane = tid & 31;
    int w = tid >> 5, wm = w & 3, wn = w >> 2;
    #pragma unroll
    for (int mt = 0; mt < 2; mt++) {
        #pragma unroll
        for (int nt = 0; nt < 8; nt++) {
            int r = m0 + wm * 32 + mt * 16 + (lane >> 2);
            int c = n0 + wn * 64 + nt * 8 + (lane & 3) * 2;
            float b0 = bo[c], b1 = bo[c + 1];
            #pragma unroll
            for (int rr = 0; rr < 2; rr++) {
                int row = r + rr * 8;
                const float* xp = x + (size_t)row * DD + c;
                float* p = out + (size_t)row * DD + c;
                float2 xv = *(const float2*)xp;
                float2 v;
                v.x = acc[mt][nt][rr * 2 + 0] + b0 + xv.x;
                v.y = acc[mt][nt][rr * 2 + 1] + b1 + xv.y;
                *(float2*)p = v;
            }
        }
    }
}

// ---------------------------------------------------------------------------
// Tensor-core flash attention (causal).
// q-tile 128 (8 warps x 16 rows), k-tile 64, bf16 mma, fp32 softmax.
// ---------------------------------------------------------------------------
#define VPITCH 72

__global__ void __launch_bounds__(256, 1) attn_mma_kernel() {
    __shared__ __nv_bfloat16 Qs[128 * VPITCH];
    __shared__ __nv_bfloat16 Ks[64 * VPITCH];
    __shared__ __nv_bfloat16 Vs[64 * VPITCH];

    int tid = threadIdx.x;
    int lane = tid & 31;
    int w = tid >> 5;                      // warp: q rows w*16..w*16+15
    int qt = gridDim.x - 1 - blockIdx.x;   // heavy tiles first
    int bh = blockIdx.y;
    int q0 = qt * 128;

    const __nv_bfloat16* Qg = g_qb + (size_t)bh * TT * HD;
    const __nv_bfloat16* Kg = g_kb + (size_t)bh * TT * HD;
    const __nv_bfloat16* Vg = g_vb + (size_t)bh * TT * HD;

    // load Q tile (128 x 64), coalesced
    #pragma unroll
    for (int u = 0; u < 4; u++) {
        int idx = u * 256 + tid;
        int r = idx >> 3, sg = (idx & 7) * 8;
        *(uint4*)(Qs + r * VPITCH + sg) = *(const uint4*)(Qg + (size_t)(q0 + r) * HD + sg);
    }
    __syncthreads();

    // Q fragments (held in regs for whole mainloop)
    uint32_t aq[4][4];
    int a_row = lane & 15, a_cg = (lane >> 4) * 8;
    uint32_t Qs_u = smem_u32(Qs);
    #pragma unroll
    for (int s = 0; s < 4; s++)
        ldm_x4(aq[s], Qs_u + (uint32_t)((w * 16 + a_row) * VPITCH + s * 16 + a_cg) * 2);

    int quad = lane >> 3;
    int b_row = (lane & 7) + ((quad & 2) ? 8 : 0);   // non-trans (K)
    int b_col = (quad & 1) ? 8 : 0;
    int t_row = (lane & 7) + ((quad & 1) ? 8 : 0);   // trans (V)
    int t_col = (quad & 2) ? 8 : 0;
    uint32_t Ks_u = smem_u32(Ks), Vs_u = smem_u32(Vs);

    float m_[2] = {-1e30f, -1e30f};
    float l_[2] = {0.f, 0.f};
    float o[8][4] = {};
    int r0g = q0 + w * 16 + (lane >> 2);   // this thread's lower q row

    int nkt = 2 * qt + 2;
    for (int kt = 0; kt < nkt; kt++) {
        __syncthreads();   // previous iteration's reads done before overwrite
        #pragma unroll
        for (int u = 0; u < 2; u++) {
            int idx = u * 256 + tid;
            int r = idx >> 3, sg = (idx & 7) * 8;
            size_t goff = (size_t)(kt * 64 + r) * HD + sg;
            *(uint4*)(Ks + r * VPITCH + sg) = *(const uint4*)(Kg + goff);
            *(uint4*)(Vs + r * VPITCH + sg) = *(const uint4*)(Vg + goff);
        }
        __syncthreads();

        // S = Q K^T  (q already scaled by 0.125)
        float s_[8][4] = {};
        #pragma unroll
        for (int s = 0; s < 4; s++) {
            #pragma unroll
            for (int nt2 = 0; nt2 < 4; nt2++) {
                uint32_t bk[4];
                ldm_x4(bk, Ks_u + (uint32_t)((nt2 * 16 + b_row) * VPITCH + s * 16 + b_col) * 2);
                mma16816(s_[nt2*2],   aq[s], bk[0], bk[1]);
                mma16816(s_[nt2*2+1], aq[s], bk[2], bk[3]);
            }
        }

        // causal mask
        if (kt * 64 + 63 > r0g) {
            #pragma unroll
            for (int nt = 0; nt < 8; nt++) {
                int c = kt * 64 + nt * 8 + (lane & 3) * 2;
                if (c     > r0g)     s_[nt][0] = -1e30f;
                if (c + 1 > r0g)     s_[nt][1] = -1e30f;
                if (c     > r0g + 8) s_[nt][2] = -1e30f;
                if (c + 1 > r0g + 8) s_[nt][3] = -1e30f;
            }
        }

        // online softmax (per-row over quad of 4 lanes)
        #pragma unroll
        for (int ri = 0; ri < 2; ri++) {
            float mx = -1e30f;
            #pragma unroll
            for (int nt = 0; nt < 8; nt++)
                mx = fmaxf(mx, fmaxf(s_[nt][ri*2], s_[nt][ri*2+1]));
            mx = fmaxf(mx, __shfl_xor_sync(0xffffffffu, mx, 1));
            mx = fmaxf(mx, __shfl_xor_sync(0xffffffffu, mx, 2));
            float mn = fmaxf(m_[ri], mx);
            float corr = __expf(m_[ri] - mn);
            m_[ri] = mn;
            float rs = 0.f;
            #pragma unroll
            for (int nt = 0; nt < 8; nt++) {
                float p0 = __expf(s_[nt][ri*2]   - mn);
                float p1 = __expf(s_[nt][ri*2+1] - mn);
                s_[nt][ri*2] = p0; s_[nt][ri*2+1] = p1;
                rs += p0 + p1;
            }
            rs += __shfl_xor_sync(0xffffffffu, rs, 1);
            rs += __shfl_xor_sync(0xffffffffu, rs, 2);
            l_[ri] = l_[ri] * corr + rs;
            #pragma unroll
            for (int nt = 0; nt < 8; nt++) {
                o[nt][ri*2]   *= corr;
                o[nt][ri*2+1] *= corr;
            }
        }

        // pack P into A-fragments (C layout == A layout trick)
        uint32_t ap[4][4];
        #pragma unroll
        for (int j = 0; j < 4; j++) {
            ap[j][0] = packbf(s_[2*j][0],   s_[2*j][1]);
            ap[j][1] = packbf(s_[2*j][2],   s_[2*j][3]);
            ap[j][2] = packbf(s_[2*j+1][0], s_[2*j+1][1]);
            ap[j][3] = packbf(s_[2*j+1][2], s_[2*j+1][3]);
        }

        // O += P V  (V^T fragments via ldmatrix.trans on [k][d] storage)
        #pragma unroll
        for (int j = 0; j < 4; j++) {
            #pragma unroll
            for (int dt2 = 0; dt2 < 4; dt2++) {
                uint32_t bv[4];
                ldm_x4_t(bv, Vs_u + (uint32_t)((j * 16 + t_row) * VPITCH + dt2 * 16 + t_col) * 2);
                mma16816(o[dt2*2],   ap[j], bv[0], bv[1]);
                mma16816(o[dt2*2+1], ap[j], bv[2], bv[3]);
            }
        }
    }

    // epilogue: normalize, split to hi/lo bf16, write [B*T, D]
    int b = bh / HH, h = bh % HH;
    #pragma unroll
    for (int ri = 0; ri < 2; ri++) {
        float inv = 1.0f / l_[ri];
        int qg = q0 + w * 16 + (lane >> 2) + ri * 8;
        size_t base = ((size_t)(b * TT + qg)) * DD + h * HD;
        #pragma unroll
        for (int nt = 0; nt < 8; nt++) {
            int c = nt * 8 + (lane & 3) * 2;
            float v0 = o[nt][ri*2] * inv, v1 = o[nt][ri*2+1] * inv;
            __nv_bfloat16 h0, l0, h1, l1;
            split_bf16(v0, h0, l0); split_bf16(v1, h1, l1);
            *(__nv_bfloat162*)(g_aoh + base + c) = __nv_bfloat162{h0, h1};
            *(__nv_bfloat162*)(g_aol + base + c) = __nv_bfloat162{l0, l1};
        }
    }
}

// ---------------------------------------------------------------------------
extern "C" void kernel_launch(void* const* d_in, const int* in_sizes, int n_in,
                              void* d_out, int out_size) {
    const float* x     = (const float*)d_in[0];
    const float* bq    = (const float*)d_in[2];
    const float* bk    = (const float*)d_in[4];
    const float* bv    = (const float*)d_in[6];
    const float* bo    = (const float*)d_in[8];
    const float* gamma = (const float*)d_in[9];
    const float* beta  = (const float*)d_in[10];
    float* out = (float*)d_out;

    ln_kernel<<<NR, 256>>>(x, gamma, beta);

    dim3 wgrid(1024, 4);
    wconv_kernel<<<wgrid, 256>>>((const float*)d_in[1], (const float*)d_in[3],
                                 (const float*)d_in[5], (const float*)d_in[7]);

    dim3 grid_qkv(DD / 128, NR / 128, 3);
    qkv_mma_kernel<<<grid_qkv, 256>>>(bq, bk, bv);

    dim3 grid_attn(TT / 128, BB * HH);
    attn_mma_kernel<<<grid_attn, 256>>>();

    dim3 grid_out(DD / 128, NR / 128);
    out_mma_kernel<<<grid_out, 256>>>(x, bo, out);
}

// round 5
// speedup vs baseline: 3.9733x; 1.1979x over previous
#include <cuda_runtime.h>
#include <cuda_bf16.h>
#include <cstdint>

#define BB 4
#define TT 2048
#define DD 1024
#define HH 16
#define HD 64
#define NR (BB*TT)   // 8192

// ---------------- device scratch (allocation-free rule) ----------------
__device__ __nv_bfloat16 g_qb[NR*DD];        // [B,H,T,HD] bf16 (q pre-scaled by 0.125)
__device__ __nv_bfloat16 g_kb[NR*DD];
__device__ __nv_bfloat16 g_vb[NR*DD];
__device__ __nv_bfloat16 g_xnh[NR*DD];       // layernormed x, bf16 hi
__device__ __nv_bfloat16 g_xnl[NR*DD];       // bf16 lo residual
__device__ __nv_bfloat16 g_aoh[NR*DD];       // attention out hi  [B*T, D]
__device__ __nv_bfloat16 g_aol[NR*DD];
__device__ __nv_bfloat16 g_wh[4u*DD*DD];     // Wq,Wk,Wv,Wo hi
__device__ __nv_bfloat16 g_wl[4u*DD*DD];     // lo

__device__ __forceinline__ uint32_t smem_u32(const void* p) {
    uint32_t a;
    asm("{ .reg .u64 t; cvta.to.shared.u64 t, %1; cvt.u32.u64 %0, t; }" : "=r"(a) : "l"(p));
    return a;
}
__device__ __forceinline__ void split_bf16(float v, __nv_bfloat16& h, __nv_bfloat16& l) {
    h = __float2bfloat16(v);
    l = __float2bfloat16(v - __bfloat162float(h));
}
__device__ __forceinline__ uint32_t packbf(float a, float b) {
    __nv_bfloat162 t = __floats2bfloat162_rn(a, b);
    return *(uint32_t*)&t;
}

// mma / ldmatrix / cp.async helpers
__device__ __forceinline__ void mma16816(float (&c)[4], const uint32_t (&a)[4],
                                         uint32_t b0, uint32_t b1) {
    asm volatile(
        "mma.sync.aligned.m16n8k16.row.col.f32.bf16.bf16.f32 "
        "{%0,%1,%2,%3},{%4,%5,%6,%7},{%8,%9},{%0,%1,%2,%3};"
        : "+f"(c[0]), "+f"(c[1]), "+f"(c[2]), "+f"(c[3])
        : "r"(a[0]), "r"(a[1]), "r"(a[2]), "r"(a[3]), "r"(b0), "r"(b1));
}
__device__ __forceinline__ void ldm_x4(uint32_t (&r)[4], uint32_t addr) {
    asm volatile("ldmatrix.sync.aligned.m8n8.x4.shared.b16 {%0,%1,%2,%3}, [%4];"
                 : "=r"(r[0]), "=r"(r[1]), "=r"(r[2]), "=r"(r[3]) : "r"(addr));
}
__device__ __forceinline__ void ldm_x4_t(uint32_t (&r)[4], uint32_t addr) {
    asm volatile("ldmatrix.sync.aligned.m8n8.x4.trans.shared.b16 {%0,%1,%2,%3}, [%4];"
                 : "=r"(r[0]), "=r"(r[1]), "=r"(r[2]), "=r"(r[3]) : "r"(addr));
}
__device__ __forceinline__ void cp16(uint32_t s, const void* g) {
    asm volatile("cp.async.cg.shared.global [%0], [%1], 16;" :: "r"(s), "l"(g));
}
__device__ __forceinline__ void cp_commit() { asm volatile("cp.async.commit_group;"); }
__device__ __forceinline__ void cp_wait1()  { asm volatile("cp.async.wait_group 1;"); }
__device__ __forceinline__ void cp_wait0()  { asm volatile("cp.async.wait_group 0;"); }

// ---------------------------------------------------------------------------
// Weight split: fp32 -> bf16 hi/lo for Wq,Wk,Wv,Wo
// ---------------------------------------------------------------------------
__global__ void wconv_kernel(const float* __restrict__ Wq, const float* __restrict__ Wk,
                             const float* __restrict__ Wv, const float* __restrict__ Wo) {
    int m = blockIdx.y;
    const float* W = (m == 0) ? Wq : (m == 1) ? Wk : (m == 2) ? Wv : Wo;
    size_t base = (size_t)m * DD * DD;
    int idx = blockIdx.x * 256 + threadIdx.x;
    float4 v = ((const float4*)W)[idx];
    __nv_bfloat16 h0, h1, h2, h3, l0, l1, l2, l3;
    split_bf16(v.x, h0, l0); split_bf16(v.y, h1, l1);
    split_bf16(v.z, h2, l2); split_bf16(v.w, h3, l3);
    __nv_bfloat162* dh = (__nv_bfloat162*)(g_wh + base + (size_t)idx * 4);
    __nv_bfloat162* dl = (__nv_bfloat162*)(g_wl + base + (size_t)idx * 4);
    dh[0] = __nv_bfloat162{h0, h1}; dh[1] = __nv_bfloat162{h2, h3};
    dl[0] = __nv_bfloat162{l0, l1}; dl[1] = __nv_bfloat162{l2, l3};
}

// ---------------------------------------------------------------------------
// LayerNorm -> bf16 hi/lo
// ---------------------------------------------------------------------------
__global__ void ln_kernel(const float* __restrict__ x,
                          const float* __restrict__ gamma,
                          const float* __restrict__ beta) {
    int row = blockIdx.x;
    int t = threadIdx.x;
    const float4* xr = (const float4*)(x + (size_t)row * DD);
    float4 v = xr[t];
    float s  = v.x + v.y + v.z + v.w;
    float sq = v.x*v.x + v.y*v.y + v.z*v.z + v.w*v.w;

    __shared__ float red0[8], red1[8];
    #pragma unroll
    for (int o = 16; o > 0; o >>= 1) {
        s  += __shfl_xor_sync(0xffffffffu, s,  o);
        sq += __shfl_xor_sync(0xffffffffu, sq, o);
    }
    int w = t >> 5, l = t & 31;
    if (l == 0) { red0[w] = s; red1[w] = sq; }
    __syncthreads();
    __shared__ float smu, srs;
    if (t < 32) {
        float a  = (t < 8) ? red0[t] : 0.f;
        float b2 = (t < 8) ? red1[t] : 0.f;
        #pragma unroll
        for (int o = 4; o > 0; o >>= 1) {
            a  += __shfl_xor_sync(0xffffffffu, a,  o);
            b2 += __shfl_xor_sync(0xffffffffu, b2, o);
        }
        if (t == 0) {
            float mu = a * (1.0f / DD);
            float var = b2 * (1.0f / DD) - mu * mu;
            smu = mu; srs = rsqrtf(var + 1e-5f);
        }
    }
    __syncthreads();
    float mu = smu, rs = srs;
    float4 gv = ((const float4*)gamma)[t];
    float4 bv = ((const float4*)beta)[t];
    float o0 = (v.x - mu) * rs * gv.x + bv.x;
    float o1 = (v.y - mu) * rs * gv.y + bv.y;
    float o2 = (v.z - mu) * rs * gv.z + bv.z;
    float o3 = (v.w - mu) * rs * gv.w + bv.w;
    __nv_bfloat16 h0,h1,h2,h3,l0,l1,l2,l3;
    split_bf16(o0,h0,l0); split_bf16(o1,h1,l1); split_bf16(o2,h2,l2); split_bf16(o3,h3,l3);
    size_t off = (size_t)row * DD + t * 4;
    ((__nv_bfloat162*)(g_xnh + off))[0] = __nv_bfloat162{h0,h1};
    ((__nv_bfloat162*)(g_xnh + off))[1] = __nv_bfloat162{h2,h3};
    ((__nv_bfloat162*)(g_xnl + off))[0] = __nv_bfloat162{l0,l1};
    ((__nv_bfloat162*)(g_xnl + off))[1] = __nv_bfloat162{l2,l3};
}

// ---------------------------------------------------------------------------
// Tensor-core GEMM core. 128x128 tile, k-chunk 32, 8 warps 4(m)x2(n).
// cp.async 2-stage pipeline. acc = (Ah+Al) @ (Bh+Bl)^T via 3 mmas.
// Stage layout (bytes): Ah @0, Al @10240, Bh @20480, Bl @30720. Row pitch 80B.
// ---------------------------------------------------------------------------
#define SPITCH 40            // elements per row (80 bytes, 16B-aligned)
#define GMATB  10240
#define GSTAGEB 40960
#define GEMM_DSMEM (2 * GSTAGEB)

__device__ __forceinline__ void gemm_issue(
    const __nv_bfloat16* Ahg, const __nv_bfloat16* Alg,
    const __nv_bfloat16* Bhg, const __nv_bfloat16* Blg,
    uint32_t base, int kc, int tid)
{
    #pragma unroll
    for (int u = 0; u < 2; u++) {
        int idx = tid * 2 + u;                 // 0..511
        int row = idx >> 2;
        int sg  = idx & 3;                     // 16B segment
        uint32_t so = (uint32_t)(row * 80 + sg * 16);
        size_t ge = (size_t)row * DD + kc * 32 + sg * 8;
        cp16(base + so,             Ahg + ge);
        cp16(base + GMATB + so,     Alg + ge);
        cp16(base + 2 * GMATB + so, Bhg + ge);
        cp16(base + 3 * GMATB + so, Blg + ge);
    }
    cp_commit();
}

__device__ __forceinline__ void gemm_core(
    const __nv_bfloat16* __restrict__ Ahg, const __nv_bfloat16* __restrict__ Alg,
    const __nv_bfloat16* __restrict__ Bhg, const __nv_bfloat16* __restrict__ Blg,
    char* dsm, float (&acc)[2][8][4], int tid)
{
    int lane = tid & 31;
    int w = tid >> 5;
    int wm = w & 3;
    int wn = w >> 2;

    uint32_t sb0 = smem_u32(dsm);
    int a_row = (lane & 15), a_cg = (lane >> 4) * 8;
    int quad = lane >> 3;
    int b_row = (lane & 7) + ((quad & 2) ? 8 : 0);
    int b_col = (quad & 1) ? 8 : 0;

    gemm_issue(Ahg, Alg, Bhg, Blg, sb0, 0, tid);

    for (int kc = 0; kc < DD / 32; kc++) {
        int s = kc & 1;
        if (kc + 1 < DD / 32) {
            gemm_issue(Ahg, Alg, Bhg, Blg, sb0 + (s ^ 1) * GSTAGEB, kc + 1, tid);
            cp_wait1();
        } else {
            cp_wait0();
        }
        __syncthreads();

        uint32_t Ah_u = sb0 + s * GSTAGEB;
        uint32_t Al_u = Ah_u + GMATB;
        uint32_t Bh_u = Ah_u + 2 * GMATB;
        uint32_t Bl_u = Ah_u + 3 * GMATB;

        #pragma unroll
        for (int ks = 0; ks < 2; ks++) {
            uint32_t ah[2][4], al[2][4];
            #pragma unroll
            for (int mt = 0; mt < 2; mt++) {
                uint32_t off = (uint32_t)((wm * 32 + mt * 16 + a_row) * SPITCH + ks * 16 + a_cg) * 2;
                ldm_x4(ah[mt], Ah_u + off);
                ldm_x4(al[mt], Al_u + off);
            }
            #pragma unroll
            for (int nt2 = 0; nt2 < 4; nt2++) {
                uint32_t boff = (uint32_t)((wn * 64 + nt2 * 16 + b_row) * SPITCH + ks * 16 + b_col) * 2;
                uint32_t bh[4], bl[4];
                ldm_x4(bh, Bh_u + boff);
                ldm_x4(bl, Bl_u + boff);
                #pragma unroll
                for (int half = 0; half < 2; half++) {
                    int nt = nt2 * 2 + half;
                    uint32_t bh0 = bh[half*2], bh1 = bh[half*2+1];
                    uint32_t bl0 = bl[half*2], bl1 = bl[half*2+1];
                    #pragma unroll
                    for (int mt = 0; mt < 2; mt++) {
                        mma16816(acc[mt][nt], ah[mt], bh0, bh1);
                        mma16816(acc[mt][nt], ah[mt], bl0, bl1);
                        mma16816(acc[mt][nt], al[mt], bh0, bh1);
                    }
                }
            }
        }
        __syncthreads();
    }
}

// ---------------------------------------------------------------------------
// QKV projection -> bf16 [B,H,T,HD]; q pre-scaled by 0.125
// ---------------------------------------------------------------------------
__global__ void __launch_bounds__(256, 2) qkv_mma_kernel(
    const float* __restrict__ bq, const float* __restrict__ bk, const float* __restrict__ bv)
{
    extern __shared__ char dsm[];
    int tid = threadIdx.x;
    int z = blockIdx.z;
    int m0 = blockIdx.y * 128;
    int n0 = blockIdx.x * 128;

    const float* bias; __nv_bfloat16* dst; float sc;
    if (z == 0)      { bias = bq; dst = g_qb; sc = 0.125f; }
    else if (z == 1) { bias = bk; dst = g_kb; sc = 1.0f; }
    else             { bias = bv; dst = g_vb; sc = 1.0f; }

    float acc[2][8][4] = {};
    gemm_core(g_xnh + (size_t)m0 * DD, g_xnl + (size_t)m0 * DD,
              g_wh + (size_t)z * DD * DD + (size_t)n0 * DD,
              g_wl + (size_t)z * DD * DD + (size_t)n0 * DD,
              dsm, acc, tid);

    int lane = tid & 31;
    int w = tid >> 5, wm = w & 3, wn = w >> 2;
    #pragma unroll
    for (int mt = 0; mt < 2; mt++) {
        #pragma unroll
        for (int nt = 0; nt < 8; nt++) {
            int r = m0 + wm * 32 + mt * 16 + (lane >> 2);
            int c = n0 + wn * 64 + nt * 8 + (lane & 3) * 2;
            float b0 = bias[c], b1 = bias[c + 1];
            #pragma unroll
            for (int rr = 0; rr < 2; rr++) {
                int row = r + rr * 8;
                int b = row >> 11, t = row & (TT - 1);
                int h = c >> 6, hd = c & 63;
                __nv_bfloat16* p = dst + (((size_t)(b * HH + h)) * TT + t) * HD + hd;
                float vx = (acc[mt][nt][rr * 2 + 0] + b0) * sc;
                float vy = (acc[mt][nt][rr * 2 + 1] + b1) * sc;
                *(__nv_bfloat162*)p = __floats2bfloat162_rn(vx, vy);
            }
        }
    }
}

// ---------------------------------------------------------------------------
// Output projection: out = x + ao @ Wo^T + bo
// ---------------------------------------------------------------------------
__global__ void __launch_bounds__(256, 2) out_mma_kernel(
    const float* __restrict__ x, const float* __restrict__ bo, float* __restrict__ out)
{
    extern __shared__ char dsm[];
    int tid = threadIdx.x;
    int m0 = blockIdx.y * 128;
    int n0 = blockIdx.x * 128;

    float acc[2][8][4] = {};
    gemm_core(g_aoh + (size_t)m0 * DD, g_aol + (size_t)m0 * DD,
              g_wh + (size_t)3 * DD * DD + (size_t)n0 * DD,
              g_wl + (size_t)3 * DD * DD + (size_t)n0 * DD,
              dsm, acc, tid);

    int lane = tid & 31;
    int w = tid >> 5, wm = w & 3, wn = w >> 2;
    #pragma unroll
    for (int mt = 0; mt < 2; mt++) {
        #pragma unroll
        for (int nt = 0; nt < 8; nt++) {
            int r = m0 + wm * 32 + mt * 16 + (lane >> 2);
            int c = n0 + wn * 64 + nt * 8 + (lane & 3) * 2;
            float b0 = bo[c], b1 = bo[c + 1];
            #pragma unroll
            for (int rr = 0; rr < 2; rr++) {
                int row = r + rr * 8;
                const float* xp = x + (size_t)row * DD + c;
                float* p = out + (size_t)row * DD + c;
                float2 xv = *(const float2*)xp;
                float2 v;
                v.x = acc[mt][nt][rr * 2 + 0] + b0 + xv.x;
                v.y = acc[mt][nt][rr * 2 + 1] + b1 + xv.y;
                *(float2*)p = v;
            }
        }
    }
}

// ---------------------------------------------------------------------------
// Tensor-core flash attention (causal).
// q-tile 128 (8 warps x 16 rows), k-tile 64, bf16 mma, fp32 softmax.
// cp.async 2-stage K/V pipeline; occupancy 2.
// ---------------------------------------------------------------------------
#define VPITCH 72                    // elements (144 B, 16B-aligned)
#define KVHALF (64 * VPITCH * 2)     // 9216 B  (one K or V tile)
#define KVSTAGE (2 * KVHALF)         // 18432 B
#define ATTN_DSMEM (2 * KVSTAGE)     // 36864 B

__global__ void __launch_bounds__(256, 2) attn_mma_kernel() {
    extern __shared__ char kvsm[];
    __shared__ __nv_bfloat16 Qs[128 * VPITCH];

    int tid = threadIdx.x;
    int lane = tid & 31;
    int w = tid >> 5;                      // warp: q rows w*16..w*16+15
    int qt = gridDim.x - 1 - blockIdx.x;   // heavy tiles first
    int bh = blockIdx.y;
    int q0 = qt * 128;

    const __nv_bfloat16* Qg = g_qb + (size_t)bh * TT * HD;
    const __nv_bfloat16* Kg = g_kb + (size_t)bh * TT * HD;
    const __nv_bfloat16* Vg = g_vb + (size_t)bh * TT * HD;

    uint32_t kv0 = smem_u32(kvsm);

    // issue K/V tile kt into stage s
    auto kv_issue = [&](int kt, int s) {
        uint32_t base = kv0 + s * KVSTAGE;
        #pragma unroll
        for (int u = 0; u < 2; u++) {
            int idx = u * 256 + tid;          // 0..511
            int r = idx >> 3, sg = idx & 7;
            size_t ge = (size_t)(kt * 64 + r) * HD + sg * 8;
            uint32_t so = (uint32_t)(r * 144 + sg * 16);
            cp16(base + so,          Kg + ge);
            cp16(base + KVHALF + so, Vg + ge);
        }
        cp_commit();
    };

    // load Q tile (128 x 64), coalesced
    #pragma unroll
    for (int u = 0; u < 4; u++) {
        int idx = u * 256 + tid;
        int r = idx >> 3, sg = (idx & 7) * 8;
        *(uint4*)(Qs + r * VPITCH + sg) = *(const uint4*)(Qg + (size_t)(q0 + r) * HD + sg);
    }

    int a_row = lane & 15, a_cg = (lane >> 4) * 8;
    uint32_t Qs_u = smem_u32(Qs);
    int quad = lane >> 3;
    int b_row = (lane & 7) + ((quad & 2) ? 8 : 0);   // non-trans (K)
    int b_col = (quad & 1) ? 8 : 0;
    int t_row = (lane & 7) + ((quad & 1) ? 8 : 0);   // trans (V)
    int t_col = (quad & 2) ? 8 : 0;

    float m_[2] = {-1e30f, -1e30f};
    float l_[2] = {0.f, 0.f};
    float o[8][4] = {};
    int r0g = q0 + w * 16 + (lane >> 2);

    int nkt = 2 * qt + 2;
    kv_issue(0, 0);

    for (int kt = 0; kt < nkt; kt++) {
        int s = kt & 1;
        if (kt + 1 < nkt) { kv_issue(kt + 1, s ^ 1); cp_wait1(); }
        else              { cp_wait0(); }
        __syncthreads();

        uint32_t Ks_u = kv0 + s * KVSTAGE;
        uint32_t Vs_u = Ks_u + KVHALF;

        // S = Q K^T  (q already scaled by 0.125)
        float s_[8][4] = {};
        #pragma unroll
        for (int sk = 0; sk < 4; sk++) {
            uint32_t aq[4];
            ldm_x4(aq, Qs_u + (uint32_t)((w * 16 + a_row) * VPITCH + sk * 16 + a_cg) * 2);
            #pragma unroll
            for (int nt2 = 0; nt2 < 4; nt2++) {
                uint32_t bk[4];
                ldm_x4(bk, Ks_u + (uint32_t)((nt2 * 16 + b_row) * VPITCH + sk * 16 + b_col) * 2);
                mma16816(s_[nt2*2],   aq, bk[0], bk[1]);
                mma16816(s_[nt2*2+1], aq, bk[2], bk[3]);
            }
        }

        // causal mask
        if (kt * 64 + 63 > r0g) {
            #pragma unroll
            for (int nt = 0; nt < 8; nt++) {
                int c = kt * 64 + nt * 8 + (lane & 3) * 2;
                if (c     > r0g)     s_[nt][0] = -1e30f;
                if (c + 1 > r0g)     s_[nt][1] = -1e30f;
                if (c     > r0g + 8) s_[nt][2] = -1e30f;
                if (c + 1 > r0g + 8) s_[nt][3] = -1e30f;
            }
        }

        // online softmax (per-row over quad of 4 lanes)
        #pragma unroll
        for (int ri = 0; ri < 2; ri++) {
            float mx = -1e30f;
            #pragma unroll
            for (int nt = 0; nt < 8; nt++)
                mx = fmaxf(mx, fmaxf(s_[nt][ri*2], s_[nt][ri*2+1]));
            mx = fmaxf(mx, __shfl_xor_sync(0xffffffffu, mx, 1));
            mx = fmaxf(mx, __shfl_xor_sync(0xffffffffu, mx, 2));
            float mn = fmaxf(m_[ri], mx);
            float corr = __expf(m_[ri] - mn);
            m_[ri] = mn;
            float rs = 0.f;
            #pragma unroll
            for (int nt = 0; nt < 8; nt++) {
                float p0 = __expf(s_[nt][ri*2]   - mn);
                float p1 = __expf(s_[nt][ri*2+1] - mn);
                s_[nt][ri*2] = p0; s_[nt][ri*2+1] = p1;
                rs += p0 + p1;
            }
            rs += __shfl_xor_sync(0xffffffffu, rs, 1);
            rs += __shfl_xor_sync(0xffffffffu, rs, 2);
            l_[ri] = l_[ri] * corr + rs;
            #pragma unroll
            for (int nt = 0; nt < 8; nt++) {
                o[nt][ri*2]   *= corr;
                o[nt][ri*2+1] *= corr;
            }
        }

        // pack P into A-fragments (C layout == A layout trick)
        uint32_t ap[4][4];
        #pragma unroll
        for (int j = 0; j < 4; j++) {
            ap[j][0] = packbf(s_[2*j][0],   s_[2*j][1]);
            ap[j][1] = packbf(s_[2*j][2],   s_[2*j][3]);
            ap[j][2] = packbf(s_[2*j+1][0], s_[2*j+1][1]);
            ap[j][3] = packbf(s_[2*j+1][2], s_[2*j+1][3]);
        }

        // O += P V  (V^T fragments via ldmatrix.trans on [k][d] storage)
        #pragma unroll
        for (int j = 0; j < 4; j++) {
            #pragma unroll
            for (int dt2 = 0; dt2 < 4; dt2++) {
                uint32_t bv[4];
                ldm_x4_t(bv, Vs_u + (uint32_t)((j * 16 + t_row) * VPITCH + dt2 * 16 + t_col) * 2);
                mma16816(o[dt2*2],   ap[j], bv[0], bv[1]);
                mma16816(o[dt2*2+1], ap[j], bv[2], bv[3]);
            }
        }
        __syncthreads();
    }

    // epilogue: normalize, split to hi/lo bf16, write [B*T, D]
    int b = bh / HH, h = bh % HH;
    #pragma unroll
    for (int ri = 0; ri < 2; ri++) {
        float inv = 1.0f / l_[ri];
        int qg = q0 + w * 16 + (lane >> 2) + ri * 8;
        size_t base = ((size_t)(b * TT + qg)) * DD + h * HD;
        #pragma unroll
        for (int nt = 0; nt < 8; nt++) {
            int c = nt * 8 + (lane & 3) * 2;
            float v0 = o[nt][ri*2] * inv, v1 = o[nt][ri*2+1] * inv;
            __nv_bfloat16 h0, l0, h1, l1;
            split_bf16(v0, h0, l0); split_bf16(v1, h1, l1);
            *(__nv_bfloat162*)(g_aoh + base + c) = __nv_bfloat162{h0, h1};
            *(__nv_bfloat162*)(g_aol + base + c) = __nv_bfloat162{l0, l1};
        }
    }
}

// ---------------------------------------------------------------------------
extern "C" void kernel_launch(void* const* d_in, const int* in_sizes, int n_in,
                              void* d_out, int out_size) {
    const float* x     = (const float*)d_in[0];
    const float* bq    = (const float*)d_in[2];
    const float* bk    = (const float*)d_in[4];
    const float* bv    = (const float*)d_in[6];
    const float* bo    = (const float*)d_in[8];
    const float* gamma = (const float*)d_in[9];
    const float* beta  = (const float*)d_in[10];
    float* out = (float*)d_out;

    cudaFuncSetAttribute(qkv_mma_kernel, cudaFuncAttributeMaxDynamicSharedMemorySize, GEMM_DSMEM);
    cudaFuncSetAttribute(out_mma_kernel, cudaFuncAttributeMaxDynamicSharedMemorySize, GEMM_DSMEM);
    cudaFuncSetAttribute(attn_mma_kernel, cudaFuncAttributeMaxDynamicSharedMemorySize, ATTN_DSMEM);

    ln_kernel<<<NR, 256>>>(x, gamma, beta);

    dim3 wgrid(1024, 4);
    wconv_kernel<<<wgrid, 256>>>((const float*)d_in[1], (const float*)d_in[3],
                                 (const float*)d_in[5], (const float*)d_in[7]);

    dim3 grid_qkv(DD / 128, NR / 128, 3);
    qkv_mma_kernel<<<grid_qkv, 256, GEMM_DSMEM>>>(bq, bk, bv);

    dim3 grid_attn(TT / 128, BB * HH);
    attn_mma_kernel<<<grid_attn, 256, ATTN_DSMEM>>>();

    dim3 grid_out(DD / 128, NR / 128);
    out_mma_kernel<<<grid_out, 256, GEMM_DSMEM>>>(x, bo, out);
}

// round 6
// speedup vs baseline: 4.9299x; 1.2408x over previous
#include <cuda_runtime.h>
#include <cuda_bf16.h>
#include <cstdint>

#define BB 4
#define TT 2048
#define DD 1024
#define HH 16
#define HD 64
#define NR (BB*TT)   // 8192

// ---------------- device scratch (allocation-free rule) ----------------
__device__ __nv_bfloat16 g_qb[NR*DD];        // [B,H,T,HD] bf16 (q pre-scaled by 0.125*log2e)
__device__ __nv_bfloat16 g_kb[NR*DD];
__device__ __nv_bfloat16 g_vb[NR*DD];
__device__ __nv_bfloat16 g_xnh[NR*DD];       // layernormed x, bf16 hi
__device__ __nv_bfloat16 g_xnl[NR*DD];       // bf16 lo residual
__device__ __nv_bfloat16 g_aoh[NR*DD];       // attention out hi  [B*T, D]
__device__ __nv_bfloat16 g_aol[NR*DD];
__device__ __nv_bfloat16 g_wh[4u*DD*DD];     // Wq,Wk,Wv,Wo hi
__device__ __nv_bfloat16 g_wl[4u*DD*DD];     // lo

__device__ __forceinline__ uint32_t smem_u32(const void* p) {
    uint32_t a;
    asm("{ .reg .u64 t; cvta.to.shared.u64 t, %1; cvt.u32.u64 %0, t; }" : "=r"(a) : "l"(p));
    return a;
}
__device__ __forceinline__ void split_bf16(float v, __nv_bfloat16& h, __nv_bfloat16& l) {
    h = __float2bfloat16(v);
    l = __float2bfloat16(v - __bfloat162float(h));
}
__device__ __forceinline__ uint32_t packbf(float a, float b) {
    __nv_bfloat162 t = __floats2bfloat162_rn(a, b);
    return *(uint32_t*)&t;
}

// mma / ldmatrix / cp.async helpers
__device__ __forceinline__ void mma16816(float (&c)[4], const uint32_t (&a)[4],
                                         uint32_t b0, uint32_t b1) {
    asm volatile(
        "mma.sync.aligned.m16n8k16.row.col.f32.bf16.bf16.f32 "
        "{%0,%1,%2,%3},{%4,%5,%6,%7},{%8,%9},{%0,%1,%2,%3};"
        : "+f"(c[0]), "+f"(c[1]), "+f"(c[2]), "+f"(c[3])
        : "r"(a[0]), "r"(a[1]), "r"(a[2]), "r"(a[3]), "r"(b0), "r"(b1));
}
__device__ __forceinline__ void ldm_x4(uint32_t (&r)[4], uint32_t addr) {
    asm volatile("ldmatrix.sync.aligned.m8n8.x4.shared.b16 {%0,%1,%2,%3}, [%4];"
                 : "=r"(r[0]), "=r"(r[1]), "=r"(r[2]), "=r"(r[3]) : "r"(addr));
}
__device__ __forceinline__ void ldm_x4_t(uint32_t (&r)[4], uint32_t addr) {
    asm volatile("ldmatrix.sync.aligned.m8n8.x4.trans.shared.b16 {%0,%1,%2,%3}, [%4];"
                 : "=r"(r[0]), "=r"(r[1]), "=r"(r[2]), "=r"(r[3]) : "r"(addr));
}
__device__ __forceinline__ void cp16(uint32_t s, const void* g) {
    asm volatile("cp.async.cg.shared.global [%0], [%1], 16;" :: "r"(s), "l"(g));
}
__device__ __forceinline__ void cp_commit() { asm volatile("cp.async.commit_group;"); }
__device__ __forceinline__ void cp_wait2()  { asm volatile("cp.async.wait_group 2;"); }
__device__ __forceinline__ void cp_wait1()  { asm volatile("cp.async.wait_group 1;"); }
__device__ __forceinline__ void cp_wait0()  { asm volatile("cp.async.wait_group 0;"); }

// ---------------------------------------------------------------------------
// Weight split: fp32 -> bf16 hi/lo for Wq,Wk,Wv,Wo
// ---------------------------------------------------------------------------
__global__ void wconv_kernel(const float* __restrict__ Wq, const float* __restrict__ Wk,
                             const float* __restrict__ Wv, const float* __restrict__ Wo) {
    int m = blockIdx.y;
    const float* W = (m == 0) ? Wq : (m == 1) ? Wk : (m == 2) ? Wv : Wo;
    size_t base = (size_t)m * DD * DD;
    int idx = blockIdx.x * 256 + threadIdx.x;
    float4 v = ((const float4*)W)[idx];
    __nv_bfloat16 h0, h1, h2, h3, l0, l1, l2, l3;
    split_bf16(v.x, h0, l0); split_bf16(v.y, h1, l1);
    split_bf16(v.z, h2, l2); split_bf16(v.w, h3, l3);
    __nv_bfloat162* dh = (__nv_bfloat162*)(g_wh + base + (size_t)idx * 4);
    __nv_bfloat162* dl = (__nv_bfloat162*)(g_wl + base + (size_t)idx * 4);
    dh[0] = __nv_bfloat162{h0, h1}; dh[1] = __nv_bfloat162{h2, h3};
    dl[0] = __nv_bfloat162{l0, l1}; dl[1] = __nv_bfloat162{l2, l3};
}

// ---------------------------------------------------------------------------
// LayerNorm -> bf16 hi/lo
// ---------------------------------------------------------------------------
__global__ void ln_kernel(const float* __restrict__ x,
                          const float* __restrict__ gamma,
                          const float* __restrict__ beta) {
    int row = blockIdx.x;
    int t = threadIdx.x;
    const float4* xr = (const float4*)(x + (size_t)row * DD);
    float4 v = xr[t];
    float s  = v.x + v.y + v.z + v.w;
    float sq = v.x*v.x + v.y*v.y + v.z*v.z + v.w*v.w;

    __shared__ float red0[8], red1[8];
    #pragma unroll
    for (int o = 16; o > 0; o >>= 1) {
        s  += __shfl_xor_sync(0xffffffffu, s,  o);
        sq += __shfl_xor_sync(0xffffffffu, sq, o);
    }
    int w = t >> 5, l = t & 31;
    if (l == 0) { red0[w] = s; red1[w] = sq; }
    __syncthreads();
    __shared__ float smu, srs;
    if (t < 32) {
        float a  = (t < 8) ? red0[t] : 0.f;
        float b2 = (t < 8) ? red1[t] : 0.f;
        #pragma unroll
        for (int o = 4; o > 0; o >>= 1) {
            a  += __shfl_xor_sync(0xffffffffu, a,  o);
            b2 += __shfl_xor_sync(0xffffffffu, b2, o);
        }
        if (t == 0) {
            float mu = a * (1.0f / DD);
            float var = b2 * (1.0f / DD) - mu * mu;
            smu = mu; srs = rsqrtf(var + 1e-5f);
        }
    }
    __syncthreads();
    float mu = smu, rs = srs;
    float4 gv = ((const float4*)gamma)[t];
    float4 bv = ((const float4*)beta)[t];
    float o0 = (v.x - mu) * rs * gv.x + bv.x;
    float o1 = (v.y - mu) * rs * gv.y + bv.y;
    float o2 = (v.z - mu) * rs * gv.z + bv.z;
    float o3 = (v.w - mu) * rs * gv.w + bv.w;
    __nv_bfloat16 h0,h1,h2,h3,l0,l1,l2,l3;
    split_bf16(o0,h0,l0); split_bf16(o1,h1,l1); split_bf16(o2,h2,l2); split_bf16(o3,h3,l3);
    size_t off = (size_t)row * DD + t * 4;
    ((__nv_bfloat162*)(g_xnh + off))[0] = __nv_bfloat162{h0,h1};
    ((__nv_bfloat162*)(g_xnh + off))[1] = __nv_bfloat162{h2,h3};
    ((__nv_bfloat162*)(g_xnl + off))[0] = __nv_bfloat162{l0,l1};
    ((__nv_bfloat162*)(g_xnl + off))[1] = __nv_bfloat162{l2,l3};
}

// ---------------------------------------------------------------------------
// Tensor-core GEMM core. 128x128 tile, k-chunk 32, 8 warps 4(m)x2(n).
// cp.async 2-stage pipeline.
// USE_BL=true : acc = (Ah+Al)@(Bh+Bl)^T via 3 mmas (hh, hl, lh)
// USE_BL=false: acc = (Ah+Al)@Bh^T via 2 mmas (hh, lh); Bl not even loaded
// Same-acc mmas spaced >=4 apart to break accumulator RAW chains.
// ---------------------------------------------------------------------------
#define SPITCH 40            // elements per row (80 bytes, 16B-aligned)
#define GMATB  10240

template <bool USE_BL>
__device__ __forceinline__ void gemm_issue(
    const __nv_bfloat16* Ahg, const __nv_bfloat16* Alg,
    const __nv_bfloat16* Bhg, const __nv_bfloat16* Blg,
    uint32_t base, int kc, int tid)
{
    #pragma unroll
    for (int u = 0; u < 2; u++) {
        int idx = tid * 2 + u;                 // 0..511
        int row = idx >> 2;
        int sg  = idx & 3;                     // 16B segment
        uint32_t so = (uint32_t)(row * 80 + sg * 16);
        size_t ge = (size_t)row * DD + kc * 32 + sg * 8;
        cp16(base + so,             Ahg + ge);
        cp16(base + GMATB + so,     Alg + ge);
        cp16(base + 2 * GMATB + so, Bhg + ge);
        if (USE_BL) cp16(base + 3 * GMATB + so, Blg + ge);
    }
    cp_commit();
}

template <bool USE_BL>
__device__ __forceinline__ void gemm_core(
    const __nv_bfloat16* __restrict__ Ahg, const __nv_bfloat16* __restrict__ Alg,
    const __nv_bfloat16* __restrict__ Bhg, const __nv_bfloat16* __restrict__ Blg,
    char* dsm, float (&acc)[2][8][4], int tid)
{
    constexpr uint32_t STAGEB = USE_BL ? 4 * GMATB : 3 * GMATB;
    int lane = tid & 31;
    int w = tid >> 5;
    int wm = w & 3;
    int wn = w >> 2;

    uint32_t sb0 = smem_u32(dsm);
    int a_row = (lane & 15), a_cg = (lane >> 4) * 8;
    int quad = lane >> 3;
    int b_row = (lane & 7) + ((quad & 2) ? 8 : 0);
    int b_col = (quad & 1) ? 8 : 0;

    gemm_issue<USE_BL>(Ahg, Alg, Bhg, Blg, sb0, 0, tid);

    for (int kc = 0; kc < DD / 32; kc++) {
        int s = kc & 1;
        if (kc + 1 < DD / 32) {
            gemm_issue<USE_BL>(Ahg, Alg, Bhg, Blg, sb0 + (s ^ 1) * STAGEB, kc + 1, tid);
            cp_wait1();
        } else {
            cp_wait0();
        }
        __syncthreads();

        uint32_t Ah_u = sb0 + s * STAGEB;
        uint32_t Al_u = Ah_u + GMATB;
        uint32_t Bh_u = Ah_u + 2 * GMATB;
        uint32_t Bl_u = Ah_u + 3 * GMATB;

        #pragma unroll
        for (int ks = 0; ks < 2; ks++) {
            uint32_t ah[2][4], al[2][4];
            #pragma unroll
            for (int mt = 0; mt < 2; mt++) {
                uint32_t off = (uint32_t)((wm * 32 + mt * 16 + a_row) * SPITCH + ks * 16 + a_cg) * 2;
                ldm_x4(ah[mt], Ah_u + off);
                ldm_x4(al[mt], Al_u + off);
            }
            #pragma unroll
            for (int nt2 = 0; nt2 < 4; nt2++) {
                uint32_t boff = (uint32_t)((wn * 64 + nt2 * 16 + b_row) * SPITCH + ks * 16 + b_col) * 2;
                uint32_t bh[4];
                ldm_x4(bh, Bh_u + boff);
                int n0t = nt2 * 2, n1t = nt2 * 2 + 1;
                // product hh — 4 independent accs
                mma16816(acc[0][n0t], ah[0], bh[0], bh[1]);
                mma16816(acc[1][n0t], ah[1], bh[0], bh[1]);
                mma16816(acc[0][n1t], ah[0], bh[2], bh[3]);
                mma16816(acc[1][n1t], ah[1], bh[2], bh[3]);
                if (USE_BL) {
                    uint32_t bl[4];
                    ldm_x4(bl, Bl_u + boff);
                    mma16816(acc[0][n0t], ah[0], bl[0], bl[1]);
                    mma16816(acc[1][n0t], ah[1], bl[0], bl[1]);
                    mma16816(acc[0][n1t], ah[0], bl[2], bl[3]);
                    mma16816(acc[1][n1t], ah[1], bl[2], bl[3]);
                }
                // product lh
                mma16816(acc[0][n0t], al[0], bh[0], bh[1]);
                mma16816(acc[1][n0t], al[1], bh[0], bh[1]);
                mma16816(acc[0][n1t], al[0], bh[2], bh[3]);
                mma16816(acc[1][n1t], al[1], bh[2], bh[3]);
            }
        }
        __syncthreads();
    }
}

#define QKV_DSMEM (2 * 3 * GMATB)   // 61440
#define OUT_DSMEM (2 * 4 * GMATB)   // 81920

// ---------------------------------------------------------------------------
// QKV projection -> bf16 [B,H,T,HD]; q pre-scaled by 0.125*log2e
// ---------------------------------------------------------------------------
__global__ void __launch_bounds__(256, 2) qkv_mma_kernel(
    const float* __restrict__ bq, const float* __restrict__ bk, const float* __restrict__ bv)
{
    extern __shared__ char dsm[];
    int tid = threadIdx.x;
    int z = blockIdx.z;
    int m0 = blockIdx.y * 128;
    int n0 = blockIdx.x * 128;

    const float* bias; __nv_bfloat16* dst; float sc;
    if (z == 0)      { bias = bq; dst = g_qb; sc = 0.125f * 1.44269504089f; }
    else if (z == 1) { bias = bk; dst = g_kb; sc = 1.0f; }
    else             { bias = bv; dst = g_vb; sc = 1.0f; }

    float acc[2][8][4] = {};
    gemm_core<false>(g_xnh + (size_t)m0 * DD, g_xnl + (size_t)m0 * DD,
                     g_wh + (size_t)z * DD * DD + (size_t)n0 * DD, nullptr,
                     dsm, acc, tid);

    int lane = tid & 31;
    int w = tid >> 5, wm = w & 3, wn = w >> 2;
    #pragma unroll
    for (int mt = 0; mt < 2; mt++) {
        #pragma unroll
        for (int nt = 0; nt < 8; nt++) {
            int r = m0 + wm * 32 + mt * 16 + (lane >> 2);
            int c = n0 + wn * 64 + nt * 8 + (lane & 3) * 2;
            float b0 = bias[c], b1 = bias[c + 1];
            #pragma unroll
            for (int rr = 0; rr < 2; rr++) {
                int row = r + rr * 8;
                int b = row >> 11, t = row & (TT - 1);
                int h = c >> 6, hd = c & 63;
                __nv_bfloat16* p = dst + (((size_t)(b * HH + h)) * TT + t) * HD + hd;
                float vx = (acc[mt][nt][rr * 2 + 0] + b0) * sc;
                float vy = (acc[mt][nt][rr * 2 + 1] + b1) * sc;
                *(__nv_bfloat162*)p = __floats2bfloat162_rn(vx, vy);
            }
        }
    }
}

// ---------------------------------------------------------------------------
// Output projection: out = x + ao @ Wo^T + bo   (full 3-mma accuracy)
// ---------------------------------------------------------------------------
__global__ void __launch_bounds__(256, 2) out_mma_kernel(
    const float* __restrict__ x, const float* __restrict__ bo, float* __restrict__ out)
{
    extern __shared__ char dsm[];
    int tid = threadIdx.x;
    int m0 = blockIdx.y * 128;
    int n0 = blockIdx.x * 128;

    float acc[2][8][4] = {};
    gemm_core<true>(g_aoh + (size_t)m0 * DD, g_aol + (size_t)m0 * DD,
                    g_wh + (size_t)3 * DD * DD + (size_t)n0 * DD,
                    g_wl + (size_t)3 * DD * DD + (size_t)n0 * DD,
                    dsm, acc, tid);

    int lane = tid & 31;
    int w = tid >> 5, wm = w & 3, wn = w >> 2;
    #pragma unroll
    for (int mt = 0; mt < 2; mt++) {
        #pragma unroll
        for (int nt = 0; nt < 8; nt++) {
            int r = m0 + wm * 32 + mt * 16 + (lane >> 2);
            int c = n0 + wn * 64 + nt * 8 + (lane & 3) * 2;
            float b0 = bo[c], b1 = bo[c + 1];
            #pragma unroll
            for (int rr = 0; rr < 2; rr++) {
                int row = r + rr * 8;
                const float* xp = x + (size_t)row * DD + c;
                float* p = out + (size_t)row * DD + c;
                float2 xv = *(const float2*)xp;
                float2 v;
                v.x = acc[mt][nt][rr * 2 + 0] + b0 + xv.x;
                v.y = acc[mt][nt][rr * 2 + 1] + b1 + xv.y;
                *(float2*)p = v;
            }
        }
    }
}

// ---------------------------------------------------------------------------
// Tensor-core flash attention (causal), exp2-domain softmax.
// q-tile 128 (8 warps x 16 rows), k-tile 64, 3-stage cp.async K/V pipeline.
// ---------------------------------------------------------------------------
#define VPITCH 72                    // elements (144 B, 16B-aligned)
#define KVHALF (64 * VPITCH * 2)     // 9216 B  (one K or V tile)
#define KVSTAGE (2 * KVHALF)         // 18432 B
#define ATTN_DSMEM (3 * KVSTAGE)     // 55296 B

__global__ void __launch_bounds__(256, 2) attn_mma_kernel() {
    extern __shared__ char kvsm[];
    __shared__ __nv_bfloat16 Qs[128 * VPITCH];

    int tid = threadIdx.x;
    int lane = tid & 31;
    int w = tid >> 5;                      // warp: q rows w*16..w*16+15
    int qt = gridDim.x - 1 - blockIdx.x;   // heavy tiles first
    int bh = blockIdx.y;
    int q0 = qt * 128;

    const __nv_bfloat16* Qg = g_qb + (size_t)bh * TT * HD;
    const __nv_bfloat16* Kg = g_kb + (size_t)bh * TT * HD;
    const __nv_bfloat16* Vg = g_vb + (size_t)bh * TT * HD;

    uint32_t kv0 = smem_u32(kvsm);

    auto kv_issue = [&](int kt, int s) {
        uint32_t base = kv0 + s * KVSTAGE;
        #pragma unroll
        for (int u = 0; u < 2; u++) {
            int idx = u * 256 + tid;          // 0..511
            int r = idx >> 3, sg = idx & 7;
            size_t ge = (size_t)(kt * 64 + r) * HD + sg * 8;
            uint32_t so = (uint32_t)(r * 144 + sg * 16);
            cp16(base + so,          Kg + ge);
            cp16(base + KVHALF + so, Vg + ge);
        }
        cp_commit();
    };

    // load Q tile (128 x 64), coalesced
    #pragma unroll
    for (int u = 0; u < 4; u++) {
        int idx = u * 256 + tid;
        int r = idx >> 3, sg = (idx & 7) * 8;
        *(uint4*)(Qs + r * VPITCH + sg) = *(const uint4*)(Qg + (size_t)(q0 + r) * HD + sg);
    }

    int a_row = lane & 15, a_cg = (lane >> 4) * 8;
    uint32_t Qs_u = smem_u32(Qs);
    int quad = lane >> 3;
    int b_row = (lane & 7) + ((quad & 2) ? 8 : 0);   // non-trans (K)
    int b_col = (quad & 1) ? 8 : 0;
    int t_row = (lane & 7) + ((quad & 1) ? 8 : 0);   // trans (V)
    int t_col = (quad & 2) ? 8 : 0;

    float m_[2] = {-1e30f, -1e30f};
    float l_[2] = {0.f, 0.f};
    float o[8][4] = {};
    int r0g = q0 + w * 16 + (lane >> 2);

    int nkt = 2 * qt + 2;
    kv_issue(0, 0);
    kv_issue(1, 1);

    for (int kt = 0; kt < nkt; kt++) {
        int s = kt % 3;
        if (kt + 2 < nkt) { kv_issue(kt + 2, (kt + 2) % 3); cp_wait2(); }
        else if (kt + 1 < nkt) { cp_wait1(); }
        else { cp_wait0(); }
        __syncthreads();

        uint32_t Ks_u = kv0 + s * KVSTAGE;
        uint32_t Vs_u = Ks_u + KVHALF;

        // S = Q K^T  (q already scaled by 0.125*log2e -> log2 domain)
        float s_[8][4] = {};
        #pragma unroll
        for (int sk = 0; sk < 4; sk++) {
            uint32_t aq[4];
            ldm_x4(aq, Qs_u + (uint32_t)((w * 16 + a_row) * VPITCH + sk * 16 + a_cg) * 2);
            #pragma unroll
            for (int nt2 = 0; nt2 < 4; nt2++) {
                uint32_t bk[4];
                ldm_x4(bk, Ks_u + (uint32_t)((nt2 * 16 + b_row) * VPITCH + sk * 16 + b_col) * 2);
                mma16816(s_[nt2*2],   aq, bk[0], bk[1]);
                mma16816(s_[nt2*2+1], aq, bk[2], bk[3]);
            }
        }

        // causal mask
        if (kt * 64 + 63 > r0g) {
            #pragma unroll
            for (int nt = 0; nt < 8; nt++) {
                int c = kt * 64 + nt * 8 + (lane & 3) * 2;
                if (c     > r0g)     s_[nt][0] = -1e30f;
                if (c + 1 > r0g)     s_[nt][1] = -1e30f;
                if (c     > r0g + 8) s_[nt][2] = -1e30f;
                if (c + 1 > r0g + 8) s_[nt][3] = -1e30f;
            }
        }

        // online softmax in exp2 domain (per-row over quad of 4 lanes)
        #pragma unroll
        for (int ri = 0; ri < 2; ri++) {
            float mx = -1e30f;
            #pragma unroll
            for (int nt = 0; nt < 8; nt++)
                mx = fmaxf(mx, fmaxf(s_[nt][ri*2], s_[nt][ri*2+1]));
            mx = fmaxf(mx, __shfl_xor_sync(0xffffffffu, mx, 1));
            mx = fmaxf(mx, __shfl_xor_sync(0xffffffffu, mx, 2));
            float mn = fmaxf(m_[ri], mx);
            float corr = exp2f(m_[ri] - mn);
            m_[ri] = mn;
            float rs = 0.f;
            #pragma unroll
            for (int nt = 0; nt < 8; nt++) {
                float p0 = exp2f(s_[nt][ri*2]   - mn);
                float p1 = exp2f(s_[nt][ri*2+1] - mn);
                s_[nt][ri*2] = p0; s_[nt][ri*2+1] = p1;
                rs += p0 + p1;
            }
            rs += __shfl_xor_sync(0xffffffffu, rs, 1);
            rs += __shfl_xor_sync(0xffffffffu, rs, 2);
            l_[ri] = l_[ri] * corr + rs;
            #pragma unroll
            for (int nt = 0; nt < 8; nt++) {
                o[nt][ri*2]   *= corr;
                o[nt][ri*2+1] *= corr;
            }
        }

        // pack P into A-fragments (C layout == A layout trick)
        uint32_t ap[4][4];
        #pragma unroll
        for (int j = 0; j < 4; j++) {
            ap[j][0] = packbf(s_[2*j][0],   s_[2*j][1]);
            ap[j][1] = packbf(s_[2*j][2],   s_[2*j][3]);
            ap[j][2] = packbf(s_[2*j+1][0], s_[2*j+1][1]);
            ap[j][3] = packbf(s_[2*j+1][2], s_[2*j+1][3]);
        }

        // O += P V  (V^T fragments via ldmatrix.trans on [k][d] storage)
        #pragma unroll
        for (int j = 0; j < 4; j++) {
            #pragma unroll
            for (int dt2 = 0; dt2 < 4; dt2++) {
                uint32_t bv[4];
                ldm_x4_t(bv, Vs_u + (uint32_t)((j * 16 + t_row) * VPITCH + dt2 * 16 + t_col) * 2);
                mma16816(o[dt2*2],   ap[j], bv[0], bv[1]);
                mma16816(o[dt2*2+1], ap[j], bv[2], bv[3]);
            }
        }
        __syncthreads();
    }

    // epilogue: normalize, split to hi/lo bf16, write [B*T, D]
    int b = bh / HH, h = bh % HH;
    #pragma unroll
    for (int ri = 0; ri < 2; ri++) {
        float inv = 1.0f / l_[ri];
        int qg = q0 + w * 16 + (lane >> 2) + ri * 8;
        size_t base = ((size_t)(b * TT + qg)) * DD + h * HD;
        #pragma unroll
        for (int nt = 0; nt < 8; nt++) {
            int c = nt * 8 + (lane & 3) * 2;
            float v0 = o[nt][ri*2] * inv, v1 = o[nt][ri*2+1] * inv;
            __nv_bfloat16 h0, l0, h1, l1;
            split_bf16(v0, h0, l0); split_bf16(v1, h1, l1);
            *(__nv_bfloat162*)(g_aoh + base + c) = __nv_bfloat162{h0, h1};
            *(__nv_bfloat162*)(g_aol + base + c) = __nv_bfloat162{l0, l1};
        }
    }
}

// ---------------------------------------------------------------------------
extern "C" void kernel_launch(void* const* d_in, const int* in_sizes, int n_in,
                              void* d_out, int out_size) {
    const float* x     = (const float*)d_in[0];
    const float* bq    = (const float*)d_in[2];
    const float* bk    = (const float*)d_in[4];
    const float* bv    = (const float*)d_in[6];
    const float* bo    = (const float*)d_in[8];
    const float* gamma = (const float*)d_in[9];
    const float* beta  = (const float*)d_in[10];
    float* out = (float*)d_out;

    cudaFuncSetAttribute(qkv_mma_kernel, cudaFuncAttributeMaxDynamicSharedMemorySize, QKV_DSMEM);
    cudaFuncSetAttribute(out_mma_kernel, cudaFuncAttributeMaxDynamicSharedMemorySize, OUT_DSMEM);
    cudaFuncSetAttribute(attn_mma_kernel, cudaFuncAttributeMaxDynamicSharedMemorySize, ATTN_DSMEM);

    ln_kernel<<<NR, 256>>>(x, gamma, beta);

    dim3 wgrid(1024, 4);
    wconv_kernel<<<wgrid, 256>>>((const float*)d_in[1], (const float*)d_in[3],
                                 (const float*)d_in[5], (const float*)d_in[7]);

    dim3 grid_qkv(DD / 128, NR / 128, 3);
    qkv_mma_kernel<<<grid_qkv, 256, QKV_DSMEM>>>(bq, bk, bv);

    dim3 grid_attn(TT / 128, BB * HH);
    attn_mma_kernel<<<grid_attn, 256, ATTN_DSMEM>>>();

    dim3 grid_out(DD / 128, NR / 128);
    out_mma_kernel<<<grid_out, 256, OUT_DSMEM>>>(x, bo, out);
}

// round 7
// speedup vs baseline: 5.2834x; 1.0717x over previous
#include <cuda_runtime.h>
#include <cuda_bf16.h>
#include <cstdint>

#define BB 4
#define TT 2048
#define DD 1024
#define HH 16
#define HD 64
#define NR (BB*TT)   // 8192

// ---------------- device scratch (allocation-free rule) ----------------
__device__ __nv_bfloat16 g_qb[NR*DD];        // [B,H,T,HD] bf16 (q pre-scaled by 0.125*log2e)
__device__ __nv_bfloat16 g_kb[NR*DD];
__device__ __nv_bfloat16 g_vb[NR*DD];
__device__ __nv_bfloat16 g_xnh[NR*DD];       // layernormed x, bf16 hi
__device__ __nv_bfloat16 g_xnl[NR*DD];       // bf16 lo residual
__device__ __nv_bfloat16 g_aoh[NR*DD];       // attention out hi  [B*T, D]
__device__ __nv_bfloat16 g_aol[NR*DD];
__device__ __nv_bfloat16 g_wh[4u*DD*DD];     // Wq,Wk,Wv,Wo hi (lo terms no longer used)

__device__ __forceinline__ uint32_t smem_u32(const void* p) {
    uint32_t a;
    asm("{ .reg .u64 t; cvta.to.shared.u64 t, %1; cvt.u32.u64 %0, t; }" : "=r"(a) : "l"(p));
    return a;
}
__device__ __forceinline__ void split_bf16(float v, __nv_bfloat16& h, __nv_bfloat16& l) {
    h = __float2bfloat16(v);
    l = __float2bfloat16(v - __bfloat162float(h));
}
__device__ __forceinline__ uint32_t packbf(float a, float b) {
    __nv_bfloat162 t = __floats2bfloat162_rn(a, b);
    return *(uint32_t*)&t;
}

// mma / ldmatrix / cp.async helpers
__device__ __forceinline__ void mma16816(float (&c)[4], const uint32_t (&a)[4],
                                         uint32_t b0, uint32_t b1) {
    asm volatile(
        "mma.sync.aligned.m16n8k16.row.col.f32.bf16.bf16.f32 "
        "{%0,%1,%2,%3},{%4,%5,%6,%7},{%8,%9},{%0,%1,%2,%3};"
        : "+f"(c[0]), "+f"(c[1]), "+f"(c[2]), "+f"(c[3])
        : "r"(a[0]), "r"(a[1]), "r"(a[2]), "r"(a[3]), "r"(b0), "r"(b1));
}
__device__ __forceinline__ void ldm_x4(uint32_t (&r)[4], uint32_t addr) {
    asm volatile("ldmatrix.sync.aligned.m8n8.x4.shared.b16 {%0,%1,%2,%3}, [%4];"
                 : "=r"(r[0]), "=r"(r[1]), "=r"(r[2]), "=r"(r[3]) : "r"(addr));
}
__device__ __forceinline__ void ldm_x4_t(uint32_t (&r)[4], uint32_t addr) {
    asm volatile("ldmatrix.sync.aligned.m8n8.x4.trans.shared.b16 {%0,%1,%2,%3}, [%4];"
                 : "=r"(r[0]), "=r"(r[1]), "=r"(r[2]), "=r"(r[3]) : "r"(addr));
}
__device__ __forceinline__ void cp16(uint32_t s, const void* g) {
    asm volatile("cp.async.cg.shared.global [%0], [%1], 16;" :: "r"(s), "l"(g));
}
__device__ __forceinline__ void cp_commit() { asm volatile("cp.async.commit_group;"); }
__device__ __forceinline__ void cp_wait1()  { asm volatile("cp.async.wait_group 1;"); }
__device__ __forceinline__ void cp_wait0()  { asm volatile("cp.async.wait_group 0;"); }

// ---------------------------------------------------------------------------
// Weight convert: fp32 -> bf16 hi for Wq,Wk,Wv,Wo
// ---------------------------------------------------------------------------
__global__ void wconv_kernel(const float* __restrict__ Wq, const float* __restrict__ Wk,
                             const float* __restrict__ Wv, const float* __restrict__ Wo) {
    int m = blockIdx.y;
    const float* W = (m == 0) ? Wq : (m == 1) ? Wk : (m == 2) ? Wv : Wo;
    size_t base = (size_t)m * DD * DD;
    int idx = blockIdx.x * 256 + threadIdx.x;
    float4 v = ((const float4*)W)[idx];
    __nv_bfloat162* dh = (__nv_bfloat162*)(g_wh + base + (size_t)idx * 4);
    dh[0] = __floats2bfloat162_rn(v.x, v.y);
    dh[1] = __floats2bfloat162_rn(v.z, v.w);
}

// ---------------------------------------------------------------------------
// LayerNorm -> bf16 hi/lo
// ---------------------------------------------------------------------------
__global__ void ln_kernel(const float* __restrict__ x,
                          const float* __restrict__ gamma,
                          const float* __restrict__ beta) {
    int row = blockIdx.x;
    int t = threadIdx.x;
    const float4* xr = (const float4*)(x + (size_t)row * DD);
    float4 v = xr[t];
    float s  = v.x + v.y + v.z + v.w;
    float sq = v.x*v.x + v.y*v.y + v.z*v.z + v.w*v.w;

    __shared__ float red0[8], red1[8];
    #pragma unroll
    for (int o = 16; o > 0; o >>= 1) {
        s  += __shfl_xor_sync(0xffffffffu, s,  o);
        sq += __shfl_xor_sync(0xffffffffu, sq, o);
    }
    int w = t >> 5, l = t & 31;
    if (l == 0) { red0[w] = s; red1[w] = sq; }
    __syncthreads();
    __shared__ float smu, srs;
    if (t < 32) {
        float a  = (t < 8) ? red0[t] : 0.f;
        float b2 = (t < 8) ? red1[t] : 0.f;
        #pragma unroll
        for (int o = 4; o > 0; o >>= 1) {
            a  += __shfl_xor_sync(0xffffffffu, a,  o);
            b2 += __shfl_xor_sync(0xffffffffu, b2, o);
        }
        if (t == 0) {
            float mu = a * (1.0f / DD);
            float var = b2 * (1.0f / DD) - mu * mu;
            smu = mu; srs = rsqrtf(var + 1e-5f);
        }
    }
    __syncthreads();
    float mu = smu, rs = srs;
    float4 gv = ((const float4*)gamma)[t];
    float4 bv = ((const float4*)beta)[t];
    float o0 = (v.x - mu) * rs * gv.x + bv.x;
    float o1 = (v.y - mu) * rs * gv.y + bv.y;
    float o2 = (v.z - mu) * rs * gv.z + bv.z;
    float o3 = (v.w - mu) * rs * gv.w + bv.w;
    __nv_bfloat16 h0,h1,h2,h3,l0,l1,l2,l3;
    split_bf16(o0,h0,l0); split_bf16(o1,h1,l1); split_bf16(o2,h2,l2); split_bf16(o3,h3,l3);
    size_t off = (size_t)row * DD + t * 4;
    ((__nv_bfloat162*)(g_xnh + off))[0] = __nv_bfloat162{h0,h1};
    ((__nv_bfloat162*)(g_xnh + off))[1] = __nv_bfloat162{h2,h3};
    ((__nv_bfloat162*)(g_xnl + off))[0] = __nv_bfloat162{l0,l1};
    ((__nv_bfloat162*)(g_xnl + off))[1] = __nv_bfloat162{l2,l3};
}

// ---------------------------------------------------------------------------
// Tensor-core GEMM core. 128x128 tile, k-chunk 32, 8 warps 4(m)x2(n).
// 3-stage cp.async pipeline, ONE __syncthreads per chunk.
// acc = (Ah+Al) @ Bh^T via 2 mmas (hh, lh); same-acc mmas spaced apart.
// Stage: Ah @0, Al @10240, Bh @20480 (30720 B). Row pitch 80B.
// ---------------------------------------------------------------------------
#define SPITCH 40            // elements per row (80 bytes)
#define GMATB  10240
#define GSTAGEB (3 * GMATB)          // 30720
#define GEMM_DSMEM (3 * GSTAGEB)     // 92160
#define NKC (DD / 32)                // 32

__device__ __forceinline__ void gemm_issue(
    const __nv_bfloat16* Ahg, const __nv_bfloat16* Alg, const __nv_bfloat16* Bhg,
    uint32_t base, int kc, int tid)
{
    #pragma unroll
    for (int u = 0; u < 2; u++) {
        int idx = tid * 2 + u;                 // 0..511
        int row = idx >> 2;
        int sg  = idx & 3;                     // 16B segment
        uint32_t so = (uint32_t)(row * 80 + sg * 16);
        size_t ge = (size_t)row * DD + kc * 32 + sg * 8;
        cp16(base + so,             Ahg + ge);
        cp16(base + GMATB + so,     Alg + ge);
        cp16(base + 2 * GMATB + so, Bhg + ge);
    }
    cp_commit();
}

__device__ __forceinline__ void gemm_core(
    const __nv_bfloat16* __restrict__ Ahg, const __nv_bfloat16* __restrict__ Alg,
    const __nv_bfloat16* __restrict__ Bhg,
    char* dsm, float (&acc)[2][8][4], int tid)
{
    int lane = tid & 31;
    int w = tid >> 5;
    int wm = w & 3;
    int wn = w >> 2;

    uint32_t sb0 = smem_u32(dsm);
    int a_row = (lane & 15), a_cg = (lane >> 4) * 8;
    int quad = lane >> 3;
    int b_row = (lane & 7) + ((quad & 2) ? 8 : 0);
    int b_col = (quad & 1) ? 8 : 0;

    gemm_issue(Ahg, Alg, Bhg, sb0,           0, tid);
    gemm_issue(Ahg, Alg, Bhg, sb0 + GSTAGEB, 1, tid);

    for (int kc = 0; kc < NKC; kc++) {
        if (kc < NKC - 1) cp_wait1(); else cp_wait0();
        __syncthreads();
        if (kc + 2 < NKC)
            gemm_issue(Ahg, Alg, Bhg, sb0 + ((kc + 2) % 3) * GSTAGEB, kc + 2, tid);

        uint32_t Ah_u = sb0 + (kc % 3) * GSTAGEB;
        uint32_t Al_u = Ah_u + GMATB;
        uint32_t Bh_u = Ah_u + 2 * GMATB;

        #pragma unroll
        for (int ks = 0; ks < 2; ks++) {
            uint32_t ah[2][4], al[2][4];
            #pragma unroll
            for (int mt = 0; mt < 2; mt++) {
                uint32_t off = (uint32_t)((wm * 32 + mt * 16 + a_row) * SPITCH + ks * 16 + a_cg) * 2;
                ldm_x4(ah[mt], Ah_u + off);
                ldm_x4(al[mt], Al_u + off);
            }
            #pragma unroll
            for (int nt2 = 0; nt2 < 4; nt2++) {
                uint32_t boff = (uint32_t)((wn * 64 + nt2 * 16 + b_row) * SPITCH + ks * 16 + b_col) * 2;
                uint32_t bh[4];
                ldm_x4(bh, Bh_u + boff);
                int n0t = nt2 * 2, n1t = nt2 * 2 + 1;
                mma16816(acc[0][n0t], ah[0], bh[0], bh[1]);
                mma16816(acc[1][n0t], ah[1], bh[0], bh[1]);
                mma16816(acc[0][n1t], ah[0], bh[2], bh[3]);
                mma16816(acc[1][n1t], ah[1], bh[2], bh[3]);
                mma16816(acc[0][n0t], al[0], bh[0], bh[1]);
                mma16816(acc[1][n0t], al[1], bh[0], bh[1]);
                mma16816(acc[0][n1t], al[0], bh[2], bh[3]);
                mma16816(acc[1][n1t], al[1], bh[2], bh[3]);
            }
        }
    }
    __syncthreads();
}

// ---------------------------------------------------------------------------
// QKV projection -> bf16 [B,H,T,HD]; q pre-scaled by 0.125*log2e
// ---------------------------------------------------------------------------
__global__ void __launch_bounds__(256, 2) qkv_mma_kernel(
    const float* __restrict__ bq, const float* __restrict__ bk, const float* __restrict__ bv)
{
    extern __shared__ char dsm[];
    int tid = threadIdx.x;
    int z = blockIdx.z;
    int m0 = blockIdx.y * 128;
    int n0 = blockIdx.x * 128;

    const float* bias; __nv_bfloat16* dst; float sc;
    if (z == 0)      { bias = bq; dst = g_qb; sc = 0.125f * 1.44269504089f; }
    else if (z == 1) { bias = bk; dst = g_kb; sc = 1.0f; }
    else             { bias = bv; dst = g_vb; sc = 1.0f; }

    float acc[2][8][4] = {};
    gemm_core(g_xnh + (size_t)m0 * DD, g_xnl + (size_t)m0 * DD,
              g_wh + (size_t)z * DD * DD + (size_t)n0 * DD,
              dsm, acc, tid);

    int lane = tid & 31;
    int w = tid >> 5, wm = w & 3, wn = w >> 2;
    #pragma unroll
    for (int mt = 0; mt < 2; mt++) {
        #pragma unroll
        for (int nt = 0; nt < 8; nt++) {
            int r = m0 + wm * 32 + mt * 16 + (lane >> 2);
            int c = n0 + wn * 64 + nt * 8 + (lane & 3) * 2;
            float b0 = bias[c], b1 = bias[c + 1];
            #pragma unroll
            for (int rr = 0; rr < 2; rr++) {
                int row = r + rr * 8;
                int b = row >> 11, t = row & (TT - 1);
                int h = c >> 6, hd = c & 63;
                __nv_bfloat16* p = dst + (((size_t)(b * HH + h)) * TT + t) * HD + hd;
                float vx = (acc[mt][nt][rr * 2 + 0] + b0) * sc;
                float vy = (acc[mt][nt][rr * 2 + 1] + b1) * sc;
                *(__nv_bfloat162*)p = __floats2bfloat162_rn(vx, vy);
            }
        }
    }
}

// ---------------------------------------------------------------------------
// Output projection: out = x + ao @ Wo^T + bo   (2-mma: (aoh+aol) @ Woh)
// ---------------------------------------------------------------------------
__global__ void __launch_bounds__(256, 2) out_mma_kernel(
    const float* __restrict__ x, const float* __restrict__ bo, float* __restrict__ out)
{
    extern __shared__ char dsm[];
    int tid = threadIdx.x;
    int m0 = blockIdx.y * 128;
    int n0 = blockIdx.x * 128;

    float acc[2][8][4] = {};
    gemm_core(g_aoh + (size_t)m0 * DD, g_aol + (size_t)m0 * DD,
              g_wh + (size_t)3 * DD * DD + (size_t)n0 * DD,
              dsm, acc, tid);

    int lane = tid & 31;
    int w = tid >> 5, wm = w & 3, wn = w >> 2;
    #pragma unroll
    for (int mt = 0; mt < 2; mt++) {
        #pragma unroll
        for (int nt = 0; nt < 8; nt++) {
            int r = m0 + wm * 32 + mt * 16 + (lane >> 2);
            int c = n0 + wn * 64 + nt * 8 + (lane & 3) * 2;
            float b0 = bo[c], b1 = bo[c + 1];
            #pragma unroll
            for (int rr = 0; rr < 2; rr++) {
                int row = r + rr * 8;
                const float* xp = x + (size_t)row * DD + c;
                float* p = out + (size_t)row * DD + c;
                float2 xv = *(const float2*)xp;
                float2 v;
                v.x = acc[mt][nt][rr * 2 + 0] + b0 + xv.x;
                v.y = acc[mt][nt][rr * 2 + 1] + b1 + xv.y;
                *(float2*)p = v;
            }
        }
    }
}

// ---------------------------------------------------------------------------
// Tensor-core flash attention (causal), exp2-domain softmax.
// q-tile 128 (8 warps x 16 rows), k-tile 64, 3-stage cp.async K/V pipeline,
// single __syncthreads per k-tile.
// ---------------------------------------------------------------------------
#define VPITCH 72                    // elements (144 B)
#define KVHALF (64 * VPITCH * 2)     // 9216 B
#define KVSTAGE (2 * KVHALF)         // 18432 B
#define ATTN_DSMEM (3 * KVSTAGE)     // 55296 B

__global__ void __launch_bounds__(256, 2) attn_mma_kernel() {
    extern __shared__ char kvsm[];
    __shared__ __nv_bfloat16 Qs[128 * VPITCH];

    int tid = threadIdx.x;
    int lane = tid & 31;
    int w = tid >> 5;
    int qt = gridDim.x - 1 - blockIdx.x;   // heavy tiles first
    int bh = blockIdx.y;
    int q0 = qt * 128;

    const __nv_bfloat16* Qg = g_qb + (size_t)bh * TT * HD;
    const __nv_bfloat16* Kg = g_kb + (size_t)bh * TT * HD;
    const __nv_bfloat16* Vg = g_vb + (size_t)bh * TT * HD;

    uint32_t kv0 = smem_u32(kvsm);

    auto kv_issue = [&](int kt, int s) {
        uint32_t base = kv0 + s * KVSTAGE;
        #pragma unroll
        for (int u = 0; u < 2; u++) {
            int idx = u * 256 + tid;
            int r = idx >> 3, sg = idx & 7;
            size_t ge = (size_t)(kt * 64 + r) * HD + sg * 8;
            uint32_t so = (uint32_t)(r * 144 + sg * 16);
            cp16(base + so,          Kg + ge);
            cp16(base + KVHALF + so, Vg + ge);
        }
        cp_commit();
    };

    int nkt = 2 * qt + 2;
    kv_issue(0, 0);
    kv_issue(1, 1);

    // load Q tile (128 x 64), coalesced
    #pragma unroll
    for (int u = 0; u < 4; u++) {
        int idx = u * 256 + tid;
        int r = idx >> 3, sg = (idx & 7) * 8;
        *(uint4*)(Qs + r * VPITCH + sg) = *(const uint4*)(Qg + (size_t)(q0 + r) * HD + sg);
    }

    int a_row = lane & 15, a_cg = (lane >> 4) * 8;
    uint32_t Qs_u = smem_u32(Qs);
    int quad = lane >> 3;
    int b_row = (lane & 7) + ((quad & 2) ? 8 : 0);   // non-trans (K)
    int b_col = (quad & 1) ? 8 : 0;
    int t_row = (lane & 7) + ((quad & 1) ? 8 : 0);   // trans (V)
    int t_col = (quad & 2) ? 8 : 0;

    float m_[2] = {-1e30f, -1e30f};
    float l_[2] = {0.f, 0.f};
    float o[8][4] = {};
    int r0g = q0 + w * 16 + (lane >> 2);

    for (int kt = 0; kt < nkt; kt++) {
        if (kt < nkt - 1) cp_wait1(); else cp_wait0();
        __syncthreads();
        if (kt + 2 < nkt) kv_issue(kt + 2, (kt + 2) % 3);

        uint32_t Ks_u = kv0 + (kt % 3) * KVSTAGE;
        uint32_t Vs_u = Ks_u + KVHALF;

        // S = Q K^T  (q already scaled -> log2 domain)
        float s_[8][4] = {};
        #pragma unroll
        for (int sk = 0; sk < 4; sk++) {
            uint32_t aq[4];
            ldm_x4(aq, Qs_u + (uint32_t)((w * 16 + a_row) * VPITCH + sk * 16 + a_cg) * 2);
            #pragma unroll
            for (int nt2 = 0; nt2 < 4; nt2++) {
                uint32_t bk[4];
                ldm_x4(bk, Ks_u + (uint32_t)((nt2 * 16 + b_row) * VPITCH + sk * 16 + b_col) * 2);
                mma16816(s_[nt2*2],   aq, bk[0], bk[1]);
                mma16816(s_[nt2*2+1], aq, bk[2], bk[3]);
            }
        }

        // causal mask
        if (kt * 64 + 63 > r0g) {
            #pragma unroll
            for (int nt = 0; nt < 8; nt++) {
                int c = kt * 64 + nt * 8 + (lane & 3) * 2;
                if (c     > r0g)     s_[nt][0] = -1e30f;
                if (c + 1 > r0g)     s_[nt][1] = -1e30f;
                if (c     > r0g + 8) s_[nt][2] = -1e30f;
                if (c + 1 > r0g + 8) s_[nt][3] = -1e30f;
            }
        }

        // online softmax in exp2 domain
        #pragma unroll
        for (int ri = 0; ri < 2; ri++) {
            float mx = -1e30f;
            #pragma unroll
            for (int nt = 0; nt < 8; nt++)
                mx = fmaxf(mx, fmaxf(s_[nt][ri*2], s_[nt][ri*2+1]));
            mx = fmaxf(mx, __shfl_xor_sync(0xffffffffu, mx, 1));
            mx = fmaxf(mx, __shfl_xor_sync(0xffffffffu, mx, 2));
            float mn = fmaxf(m_[ri], mx);
            float corr = exp2f(m_[ri] - mn);
            m_[ri] = mn;
            float rs = 0.f;
            #pragma unroll
            for (int nt = 0; nt < 8; nt++) {
                float p0 = exp2f(s_[nt][ri*2]   - mn);
                float p1 = exp2f(s_[nt][ri*2+1] - mn);
                s_[nt][ri*2] = p0; s_[nt][ri*2+1] = p1;
                rs += p0 + p1;
            }
            rs += __shfl_xor_sync(0xffffffffu, rs, 1);
            rs += __shfl_xor_sync(0xffffffffu, rs, 2);
            l_[ri] = l_[ri] * corr + rs;
            #pragma unroll
            for (int nt = 0; nt < 8; nt++) {
                o[nt][ri*2]   *= corr;
                o[nt][ri*2+1] *= corr;
            }
        }

        // pack P into A-fragments
        uint32_t ap[4][4];
        #pragma unroll
        for (int j = 0; j < 4; j++) {
            ap[j][0] = packbf(s_[2*j][0],   s_[2*j][1]);
            ap[j][1] = packbf(s_[2*j][2],   s_[2*j][3]);
            ap[j][2] = packbf(s_[2*j+1][0], s_[2*j+1][1]);
            ap[j][3] = packbf(s_[2*j+1][2], s_[2*j+1][3]);
        }

        // O += P V
        #pragma unroll
        for (int j = 0; j < 4; j++) {
            #pragma unroll
            for (int dt2 = 0; dt2 < 4; dt2++) {
                uint32_t bv[4];
                ldm_x4_t(bv, Vs_u + (uint32_t)((j * 16 + t_row) * VPITCH + dt2 * 16 + t_col) * 2);
                mma16816(o[dt2*2],   ap[j], bv[0], bv[1]);
                mma16816(o[dt2*2+1], ap[j], bv[2], bv[3]);
            }
        }
    }

    // epilogue: normalize, split to hi/lo bf16, write [B*T, D]
    int b = bh / HH, h = bh % HH;
    #pragma unroll
    for (int ri = 0; ri < 2; ri++) {
        float inv = 1.0f / l_[ri];
        int qg = q0 + w * 16 + (lane >> 2) + ri * 8;
        size_t base = ((size_t)(b * TT + qg)) * DD + h * HD;
        #pragma unroll
        for (int nt = 0; nt < 8; nt++) {
            int c = nt * 8 + (lane & 3) * 2;
            float v0 = o[nt][ri*2] * inv, v1 = o[nt][ri*2+1] * inv;
            __nv_bfloat16 h0, l0, h1, l1;
            split_bf16(v0, h0, l0); split_bf16(v1, h1, l1);
            *(__nv_bfloat162*)(g_aoh + base + c) = __nv_bfloat162{h0, h1};
            *(__nv_bfloat162*)(g_aol + base + c) = __nv_bfloat162{l0, l1};
        }
    }
}

// ---------------------------------------------------------------------------
extern "C" void kernel_launch(void* const* d_in, const int* in_sizes, int n_in,
                              void* d_out, int out_size) {
    const float* x     = (const float*)d_in[0];
    const float* bq    = (const float*)d_in[2];
    const float* bk    = (const float*)d_in[4];
    const float* bv    = (const float*)d_in[6];
    const float* bo    = (const float*)d_in[8];
    const float* gamma = (const float*)d_in[9];
    const float* beta  = (const float*)d_in[10];
    float* out = (float*)d_out;

    cudaFuncSetAttribute(qkv_mma_kernel, cudaFuncAttributeMaxDynamicSharedMemorySize, GEMM_DSMEM);
    cudaFuncSetAttribute(out_mma_kernel, cudaFuncAttributeMaxDynamicSharedMemorySize, GEMM_DSMEM);
    cudaFuncSetAttribute(attn_mma_kernel, cudaFuncAttributeMaxDynamicSharedMemorySize, ATTN_DSMEM);

    ln_kernel<<<NR, 256>>>(x, gamma, beta);

    dim3 wgrid(1024, 4);
    wconv_kernel<<<wgrid, 256>>>((const float*)d_in[1], (const float*)d_in[3],
                                 (const float*)d_in[5], (const float*)d_in[7]);

    dim3 grid_qkv(DD / 128, NR / 128, 3);
    qkv_mma_kernel<<<grid_qkv, 256, GEMM_DSMEM>>>(bq, bk, bv);

    dim3 grid_attn(TT / 128, BB * HH);
    attn_mma_kernel<<<grid_attn, 256, ATTN_DSMEM>>>();

    dim3 grid_out(DD / 128, NR / 128);
    out_mma_kernel<<<grid_out, 256, GEMM_DSMEM>>>(x, bo, out);
}

// round 8
// speedup vs baseline: 6.7298x; 1.2738x over previous
#include <cuda_runtime.h>
#include <cuda_bf16.h>
#include <cstdint>

#define BB 4
#define TT 2048
#define DD 1024
#define HH 16
#define HD 64
#define NR (BB*TT)   // 8192

// ---------------- device scratch (allocation-free rule) ----------------
__device__ __nv_bfloat16 g_qb[NR*DD];        // [B,H,T,HD] bf16 (q pre-scaled by 0.125*log2e)
__device__ __nv_bfloat16 g_kb[NR*DD];
__device__ __nv_bfloat16 g_vb[NR*DD];
__device__ __nv_bfloat16 g_xnh[NR*DD];       // layernormed x, bf16
__device__ __nv_bfloat16 g_aoh[NR*DD];       // attention out hi  [B*T, D]
__device__ __nv_bfloat16 g_aol[NR*DD];       // attention out lo
__device__ __nv_bfloat16 g_wh[4u*DD*DD];     // Wq,Wk,Wv,Wo bf16

__device__ __forceinline__ uint32_t smem_u32(const void* p) {
    uint32_t a;
    asm("{ .reg .u64 t; cvta.to.shared.u64 t, %1; cvt.u32.u64 %0, t; }" : "=r"(a) : "l"(p));
    return a;
}
__device__ __forceinline__ void split_bf16(float v, __nv_bfloat16& h, __nv_bfloat16& l) {
    h = __float2bfloat16(v);
    l = __float2bfloat16(v - __bfloat162float(h));
}
__device__ __forceinline__ uint32_t packbf(float a, float b) {
    __nv_bfloat162 t = __floats2bfloat162_rn(a, b);
    return *(uint32_t*)&t;
}

// mma / ldmatrix / cp.async helpers
__device__ __forceinline__ void mma16816(float (&c)[4], const uint32_t (&a)[4],
                                         uint32_t b0, uint32_t b1) {
    asm volatile(
        "mma.sync.aligned.m16n8k16.row.col.f32.bf16.bf16.f32 "
        "{%0,%1,%2,%3},{%4,%5,%6,%7},{%8,%9},{%0,%1,%2,%3};"
        : "+f"(c[0]), "+f"(c[1]), "+f"(c[2]), "+f"(c[3])
        : "r"(a[0]), "r"(a[1]), "r"(a[2]), "r"(a[3]), "r"(b0), "r"(b1));
}
__device__ __forceinline__ void ldm_x4(uint32_t (&r)[4], uint32_t addr) {
    asm volatile("ldmatrix.sync.aligned.m8n8.x4.shared.b16 {%0,%1,%2,%3}, [%4];"
                 : "=r"(r[0]), "=r"(r[1]), "=r"(r[2]), "=r"(r[3]) : "r"(addr));
}
__device__ __forceinline__ void ldm_x4_t(uint32_t (&r)[4], uint32_t addr) {
    asm volatile("ldmatrix.sync.aligned.m8n8.x4.trans.shared.b16 {%0,%1,%2,%3}, [%4];"
                 : "=r"(r[0]), "=r"(r[1]), "=r"(r[2]), "=r"(r[3]) : "r"(addr));
}
__device__ __forceinline__ void cp16(uint32_t s, const void* g) {
    asm volatile("cp.async.cg.shared.global [%0], [%1], 16;" :: "r"(s), "l"(g));
}
__device__ __forceinline__ void cp_commit() { asm volatile("cp.async.commit_group;"); }
__device__ __forceinline__ void cp_wait1()  { asm volatile("cp.async.wait_group 1;"); }
__device__ __forceinline__ void cp_wait0()  { asm volatile("cp.async.wait_group 0;"); }

// ---------------------------------------------------------------------------
// Weight convert: fp32 -> bf16 for Wq,Wk,Wv,Wo
// ---------------------------------------------------------------------------
__global__ void wconv_kernel(const float* __restrict__ Wq, const float* __restrict__ Wk,
                             const float* __restrict__ Wv, const float* __restrict__ Wo) {
    int m = blockIdx.y;
    const float* W = (m == 0) ? Wq : (m == 1) ? Wk : (m == 2) ? Wv : Wo;
    size_t base = (size_t)m * DD * DD;
    int idx = blockIdx.x * 256 + threadIdx.x;
    float4 v = ((const float4*)W)[idx];
    __nv_bfloat162* dh = (__nv_bfloat162*)(g_wh + base + (size_t)idx * 4);
    dh[0] = __floats2bfloat162_rn(v.x, v.y);
    dh[1] = __floats2bfloat162_rn(v.z, v.w);
}

// ---------------------------------------------------------------------------
// LayerNorm -> bf16
// ---------------------------------------------------------------------------
__global__ void ln_kernel(const float* __restrict__ x,
                          const float* __restrict__ gamma,
                          const float* __restrict__ beta) {
    int row = blockIdx.x;
    int t = threadIdx.x;
    const float4* xr = (const float4*)(x + (size_t)row * DD);
    float4 v = xr[t];
    float s  = v.x + v.y + v.z + v.w;
    float sq = v.x*v.x + v.y*v.y + v.z*v.z + v.w*v.w;

    __shared__ float red0[8], red1[8];
    #pragma unroll
    for (int o = 16; o > 0; o >>= 1) {
        s  += __shfl_xor_sync(0xffffffffu, s,  o);
        sq += __shfl_xor_sync(0xffffffffu, sq, o);
    }
    int w = t >> 5, l = t & 31;
    if (l == 0) { red0[w] = s; red1[w] = sq; }
    __syncthreads();
    __shared__ float smu, srs;
    if (t < 32) {
        float a  = (t < 8) ? red0[t] : 0.f;
        float b2 = (t < 8) ? red1[t] : 0.f;
        #pragma unroll
        for (int o = 4; o > 0; o >>= 1) {
            a  += __shfl_xor_sync(0xffffffffu, a,  o);
            b2 += __shfl_xor_sync(0xffffffffu, b2, o);
        }
        if (t == 0) {
            float mu = a * (1.0f / DD);
            float var = b2 * (1.0f / DD) - mu * mu;
            smu = mu; srs = rsqrtf(var + 1e-5f);
        }
    }
    __syncthreads();
    float mu = smu, rs = srs;
    float4 gv = ((const float4*)gamma)[t];
    float4 bv = ((const float4*)beta)[t];
    float o0 = (v.x - mu) * rs * gv.x + bv.x;
    float o1 = (v.y - mu) * rs * gv.y + bv.y;
    float o2 = (v.z - mu) * rs * gv.z + bv.z;
    float o3 = (v.w - mu) * rs * gv.w + bv.w;
    size_t off = (size_t)row * DD + t * 4;
    ((__nv_bfloat162*)(g_xnh + off))[0] = __floats2bfloat162_rn(o0, o1);
    ((__nv_bfloat162*)(g_xnh + off))[1] = __floats2bfloat162_rn(o2, o3);
}

// ---------------------------------------------------------------------------
// Tensor-core GEMM core. 128x128 tile, k-chunk 32, 8 warps 4(m)x2(n).
// 3-stage cp.async pipeline, ONE __syncthreads per chunk.
// USE_AL=false: acc = Ah @ Bh^T (1 mma)   — stage: Ah, Bh (20480 B)
// USE_AL=true : acc = (Ah+Al) @ Bh^T (2)  — stage: Ah, Al, Bh (30720 B)
// ---------------------------------------------------------------------------
#define SPITCH 40            // elements per row (80 bytes)
#define GMATB  10240
#define NKC (DD / 32)        // 32

template <bool USE_AL>
__device__ __forceinline__ void gemm_issue(
    const __nv_bfloat16* Ahg, const __nv_bfloat16* Alg, const __nv_bfloat16* Bhg,
    uint32_t base, int kc, int tid)
{
    constexpr uint32_t BOFF = USE_AL ? 2u * GMATB : 1u * GMATB;
    #pragma unroll
    for (int u = 0; u < 2; u++) {
        int idx = tid * 2 + u;                 // 0..511
        int row = idx >> 2;
        int sg  = idx & 3;                     // 16B segment
        uint32_t so = (uint32_t)(row * 80 + sg * 16);
        size_t ge = (size_t)row * DD + kc * 32 + sg * 8;
        cp16(base + so,        Ahg + ge);
        if (USE_AL) cp16(base + GMATB + so, Alg + ge);
        cp16(base + BOFF + so, Bhg + ge);
    }
    cp_commit();
}

template <bool USE_AL>
__device__ __forceinline__ void gemm_core(
    const __nv_bfloat16* __restrict__ Ahg, const __nv_bfloat16* __restrict__ Alg,
    const __nv_bfloat16* __restrict__ Bhg,
    char* dsm, float (&acc)[2][8][4], int tid)
{
    constexpr uint32_t STAGEB = USE_AL ? 3u * GMATB : 2u * GMATB;
    constexpr uint32_t BOFF   = USE_AL ? 2u * GMATB : 1u * GMATB;
    int lane = tid & 31;
    int w = tid >> 5;
    int wm = w & 3;
    int wn = w >> 2;

    uint32_t sb0 = smem_u32(dsm);
    int a_row = (lane & 15), a_cg = (lane >> 4) * 8;
    int quad = lane >> 3;
    int b_row = (lane & 7) + ((quad & 2) ? 8 : 0);
    int b_col = (quad & 1) ? 8 : 0;

    gemm_issue<USE_AL>(Ahg, Alg, Bhg, sb0,          0, tid);
    gemm_issue<USE_AL>(Ahg, Alg, Bhg, sb0 + STAGEB, 1, tid);

    for (int kc = 0; kc < NKC; kc++) {
        if (kc < NKC - 1) cp_wait1(); else cp_wait0();
        __syncthreads();
        if (kc + 2 < NKC)
            gemm_issue<USE_AL>(Ahg, Alg, Bhg, sb0 + ((kc + 2) % 3) * STAGEB, kc + 2, tid);

        uint32_t Ah_u = sb0 + (kc % 3) * STAGEB;
        uint32_t Al_u = Ah_u + GMATB;
        uint32_t Bh_u = Ah_u + BOFF;

        #pragma unroll
        for (int ks = 0; ks < 2; ks++) {
            uint32_t ah[2][4], al[2][4];
            #pragma unroll
            for (int mt = 0; mt < 2; mt++) {
                uint32_t off = (uint32_t)((wm * 32 + mt * 16 + a_row) * SPITCH + ks * 16 + a_cg) * 2;
                ldm_x4(ah[mt], Ah_u + off);
                if (USE_AL) ldm_x4(al[mt], Al_u + off);
            }
            #pragma unroll
            for (int nt2 = 0; nt2 < 4; nt2++) {
                uint32_t boff = (uint32_t)((wn * 64 + nt2 * 16 + b_row) * SPITCH + ks * 16 + b_col) * 2;
                uint32_t bh[4];
                ldm_x4(bh, Bh_u + boff);
                int n0t = nt2 * 2, n1t = nt2 * 2 + 1;
                mma16816(acc[0][n0t], ah[0], bh[0], bh[1]);
                mma16816(acc[1][n0t], ah[1], bh[0], bh[1]);
                mma16816(acc[0][n1t], ah[0], bh[2], bh[3]);
                mma16816(acc[1][n1t], ah[1], bh[2], bh[3]);
                if (USE_AL) {
                    mma16816(acc[0][n0t], al[0], bh[0], bh[1]);
                    mma16816(acc[1][n0t], al[1], bh[0], bh[1]);
                    mma16816(acc[0][n1t], al[0], bh[2], bh[3]);
                    mma16816(acc[1][n1t], al[1], bh[2], bh[3]);
                }
            }
        }
    }
    __syncthreads();
}

#define QKV_DSMEM (3 * 2 * GMATB)   // 61440
#define OUT_DSMEM (3 * 3 * GMATB)   // 92160

// ---------------------------------------------------------------------------
// QKV projection -> bf16 [B,H,T,HD]; q pre-scaled by 0.125*log2e
// ---------------------------------------------------------------------------
__global__ void __launch_bounds__(256, 2) qkv_mma_kernel(
    const float* __restrict__ bq, const float* __restrict__ bk, const float* __restrict__ bv)
{
    extern __shared__ char dsm[];
    int tid = threadIdx.x;
    int z = blockIdx.z;
    int m0 = blockIdx.y * 128;
    int n0 = blockIdx.x * 128;

    const float* bias; __nv_bfloat16* dst; float sc;
    if (z == 0)      { bias = bq; dst = g_qb; sc = 0.125f * 1.44269504089f; }
    else if (z == 1) { bias = bk; dst = g_kb; sc = 1.0f; }
    else             { bias = bv; dst = g_vb; sc = 1.0f; }

    float acc[2][8][4] = {};
    gemm_core<false>(g_xnh + (size_t)m0 * DD, nullptr,
                     g_wh + (size_t)z * DD * DD + (size_t)n0 * DD,
                     dsm, acc, tid);

    int lane = tid & 31;
    int w = tid >> 5, wm = w & 3, wn = w >> 2;
    #pragma unroll
    for (int mt = 0; mt < 2; mt++) {
        #pragma unroll
        for (int nt = 0; nt < 8; nt++) {
            int r = m0 + wm * 32 + mt * 16 + (lane >> 2);
            int c = n0 + wn * 64 + nt * 8 + (lane & 3) * 2;
            float b0 = bias[c], b1 = bias[c + 1];
            #pragma unroll
            for (int rr = 0; rr < 2; rr++) {
                int row = r + rr * 8;
                int b = row >> 11, t = row & (TT - 1);
                int h = c >> 6, hd = c & 63;
                __nv_bfloat16* p = dst + (((size_t)(b * HH + h)) * TT + t) * HD + hd;
                float vx = (acc[mt][nt][rr * 2 + 0] + b0) * sc;
                float vy = (acc[mt][nt][rr * 2 + 1] + b1) * sc;
                *(__nv_bfloat162*)p = __floats2bfloat162_rn(vx, vy);
            }
        }
    }
}

// ---------------------------------------------------------------------------
// Output projection: out = x + ao @ Wo^T + bo   ((aoh+aol) @ Wo, 2 mmas)
// ---------------------------------------------------------------------------
__global__ void __launch_bounds__(256, 2) out_mma_kernel(
    const float* __restrict__ x, const float* __restrict__ bo, float* __restrict__ out)
{
    extern __shared__ char dsm[];
    int tid = threadIdx.x;
    int m0 = blockIdx.y * 128;
    int n0 = blockIdx.x * 128;

    float acc[2][8][4] = {};
    gemm_core<true>(g_aoh + (size_t)m0 * DD, g_aol + (size_t)m0 * DD,
                    g_wh + (size_t)3 * DD * DD + (size_t)n0 * DD,
                    dsm, acc, tid);

    int lane = tid & 31;
    int w = tid >> 5, wm = w & 3, wn = w >> 2;
    #pragma unroll
    for (int mt = 0; mt < 2; mt++) {
        #pragma unroll
        for (int nt = 0; nt < 8; nt++) {
            int r = m0 + wm * 32 + mt * 16 + (lane >> 2);
            int c = n0 + wn * 64 + nt * 8 + (lane & 3) * 2;
            float b0 = bo[c], b1 = bo[c + 1];
            #pragma unroll
            for (int rr = 0; rr < 2; rr++) {
                int row = r + rr * 8;
                const float* xp = x + (size_t)row * DD + c;
                float* p = out + (size_t)row * DD + c;
                float2 xv = *(const float2*)xp;
                float2 v;
                v.x = acc[mt][nt][rr * 2 + 0] + b0 + xv.x;
                v.y = acc[mt][nt][rr * 2 + 1] + b1 + xv.y;
                *(float2*)p = v;
            }
        }
    }
}

// ---------------------------------------------------------------------------
// Tensor-core flash attention (causal), exp2-domain softmax.
// q-tile 128 (8 warps x 16 rows), k-tile 64, 3-stage cp.async K/V pipeline,
// single __syncthreads per k-tile.
// ---------------------------------------------------------------------------
#define VPITCH 72                    // elements (144 B)
#define KVHALF (64 * VPITCH * 2)     // 9216 B
#define KVSTAGE (2 * KVHALF)         // 18432 B
#define ATTN_DSMEM (3 * KVSTAGE)     // 55296 B

__global__ void __launch_bounds__(256, 2) attn_mma_kernel() {
    extern __shared__ char kvsm[];
    __shared__ __nv_bfloat16 Qs[128 * VPITCH];

    int tid = threadIdx.x;
    int lane = tid & 31;
    int w = tid >> 5;
    int qt = gridDim.x - 1 - blockIdx.x;   // heavy tiles first
    int bh = blockIdx.y;
    int q0 = qt * 128;

    const __nv_bfloat16* Qg = g_qb + (size_t)bh * TT * HD;
    const __nv_bfloat16* Kg = g_kb + (size_t)bh * TT * HD;
    const __nv_bfloat16* Vg = g_vb + (size_t)bh * TT * HD;

    uint32_t kv0 = smem_u32(kvsm);

    auto kv_issue = [&](int kt, int s) {
        uint32_t base = kv0 + s * KVSTAGE;
        #pragma unroll
        for (int u = 0; u < 2; u++) {
            int idx = u * 256 + tid;
            int r = idx >> 3, sg = idx & 7;
            size_t ge = (size_t)(kt * 64 + r) * HD + sg * 8;
            uint32_t so = (uint32_t)(r * 144 + sg * 16);
            cp16(base + so,          Kg + ge);
            cp16(base + KVHALF + so, Vg + ge);
        }
        cp_commit();
    };

    int nkt = 2 * qt + 2;
    kv_issue(0, 0);
    kv_issue(1, 1);

    // load Q tile (128 x 64), coalesced
    #pragma unroll
    for (int u = 0; u < 4; u++) {
        int idx = u * 256 + tid;
        int r = idx >> 3, sg = (idx & 7) * 8;
        *(uint4*)(Qs + r * VPITCH + sg) = *(const uint4*)(Qg + (size_t)(q0 + r) * HD + sg);
    }

    int a_row = lane & 15, a_cg = (lane >> 4) * 8;
    uint32_t Qs_u = smem_u32(Qs);
    int quad = lane >> 3;
    int b_row = (lane & 7) + ((quad & 2) ? 8 : 0);   // non-trans (K)
    int b_col = (quad & 1) ? 8 : 0;
    int t_row = (lane & 7) + ((quad & 1) ? 8 : 0);   // trans (V)
    int t_col = (quad & 2) ? 8 : 0;

    float m_[2] = {-1e30f, -1e30f};
    float l_[2] = {0.f, 0.f};
    float o[8][4] = {};
    int r0g = q0 + w * 16 + (lane >> 2);

    for (int kt = 0; kt < nkt; kt++) {
        if (kt < nkt - 1) cp_wait1(); else cp_wait0();
        __syncthreads();
        if (kt + 2 < nkt) kv_issue(kt + 2, (kt + 2) % 3);

        uint32_t Ks_u = kv0 + (kt % 3) * KVSTAGE;
        uint32_t Vs_u = Ks_u + KVHALF;

        // S = Q K^T  (q already scaled -> log2 domain)
        float s_[8][4] = {};
        #pragma unroll
        for (int sk = 0; sk < 4; sk++) {
            uint32_t aq[4];
            ldm_x4(aq, Qs_u + (uint32_t)((w * 16 + a_row) * VPITCH + sk * 16 + a_cg) * 2);
            #pragma unroll
            for (int nt2 = 0; nt2 < 4; nt2++) {
                uint32_t bk[4];
                ldm_x4(bk, Ks_u + (uint32_t)((nt2 * 16 + b_row) * VPITCH + sk * 16 + b_col) * 2);
                mma16816(s_[nt2*2],   aq, bk[0], bk[1]);
                mma16816(s_[nt2*2+1], aq, bk[2], bk[3]);
            }
        }

        // causal mask
        if (kt * 64 + 63 > r0g) {
            #pragma unroll
            for (int nt = 0; nt < 8; nt++) {
                int c = kt * 64 + nt * 8 + (lane & 3) * 2;
                if (c     > r0g)     s_[nt][0] = -1e30f;
                if (c + 1 > r0g)     s_[nt][1] = -1e30f;
                if (c     > r0g + 8) s_[nt][2] = -1e30f;
                if (c + 1 > r0g + 8) s_[nt][3] = -1e30f;
            }
        }

        // online softmax in exp2 domain
        #pragma unroll
        for (int ri = 0; ri < 2; ri++) {
            float mx = -1e30f;
            #pragma unroll
            for (int nt = 0; nt < 8; nt++)
                mx = fmaxf(mx, fmaxf(s_[nt][ri*2], s_[nt][ri*2+1]));
            mx = fmaxf(mx, __shfl_xor_sync(0xffffffffu, mx, 1));
            mx = fmaxf(mx, __shfl_xor_sync(0xffffffffu, mx, 2));
            float mn = fmaxf(m_[ri], mx);
            float corr = exp2f(m_[ri] - mn);
            m_[ri] = mn;
            float rs = 0.f;
            #pragma unroll
            for (int nt = 0; nt < 8; nt++) {
                float p0 = exp2f(s_[nt][ri*2]   - mn);
                float p1 = exp2f(s_[nt][ri*2+1] - mn);
                s_[nt][ri*2] = p0; s_[nt][ri*2+1] = p1;
                rs += p0 + p1;
            }
            rs += __shfl_xor_sync(0xffffffffu, rs, 1);
            rs += __shfl_xor_sync(0xffffffffu, rs, 2);
            l_[ri] = l_[ri] * corr + rs;
            #pragma unroll
            for (int nt = 0; nt < 8; nt++) {
                o[nt][ri*2]   *= corr;
                o[nt][ri*2+1] *= corr;
            }
        }

        // pack P into A-fragments
        uint32_t ap[4][4];
        #pragma unroll
        for (int j = 0; j < 4; j++) {
            ap[j][0] = packbf(s_[2*j][0],   s_[2*j][1]);
            ap[j][1] = packbf(s_[2*j][2],   s_[2*j][3]);
            ap[j][2] = packbf(s_[2*j+1][0], s_[2*j+1][1]);
            ap[j][3] = packbf(s_[2*j+1][2], s_[2*j+1][3]);
        }

        // O += P V
        #pragma unroll
        for (int j = 0; j < 4; j++) {
            #pragma unroll
            for (int dt2 = 0; dt2 < 4; dt2++) {
                uint32_t bv[4];
                ldm_x4_t(bv, Vs_u + (uint32_t)((j * 16 + t_row) * VPITCH + dt2 * 16 + t_col) * 2);
                mma16816(o[dt2*2],   ap[j], bv[0], bv[1]);
                mma16816(o[dt2*2+1], ap[j], bv[2], bv[3]);
            }
        }
    }

    // epilogue: normalize, split to hi/lo bf16, write [B*T, D]
    int b = bh / HH, h = bh % HH;
    #pragma unroll
    for (int ri = 0; ri < 2; ri++) {
        float inv = 1.0f / l_[ri];
        int qg = q0 + w * 16 + (lane >> 2) + ri * 8;
        size_t base = ((size_t)(b * TT + qg)) * DD + h * HD;
        #pragma unroll
        for (int nt = 0; nt < 8; nt++) {
            int c = nt * 8 + (lane & 3) * 2;
            float v0 = o[nt][ri*2] * inv, v1 = o[nt][ri*2+1] * inv;
            __nv_bfloat16 h0, l0, h1, l1;
            split_bf16(v0, h0, l0); split_bf16(v1, h1, l1);
            *(__nv_bfloat162*)(g_aoh + base + c) = __nv_bfloat162{h0, h1};
            *(__nv_bfloat162*)(g_aol + base + c) = __nv_bfloat162{l0, l1};
        }
    }
}

// ---------------------------------------------------------------------------
extern "C" void kernel_launch(void* const* d_in, const int* in_sizes, int n_in,
                              void* d_out, int out_size) {
    const float* x     = (const float*)d_in[0];
    const float* bq    = (const float*)d_in[2];
    const float* bk    = (const float*)d_in[4];
    const float* bv    = (const float*)d_in[6];
    const float* bo    = (const float*)d_in[8];
    const float* gamma = (const float*)d_in[9];
    const float* beta  = (const float*)d_in[10];
    float* out = (float*)d_out;

    cudaFuncSetAttribute(qkv_mma_kernel, cudaFuncAttributeMaxDynamicSharedMemorySize, QKV_DSMEM);
    cudaFuncSetAttribute(out_mma_kernel, cudaFuncAttributeMaxDynamicSharedMemorySize, OUT_DSMEM);
    cudaFuncSetAttribute(attn_mma_kernel, cudaFuncAttributeMaxDynamicSharedMemorySize, ATTN_DSMEM);

    ln_kernel<<<NR, 256>>>(x, gamma, beta);

    dim3 wgrid(1024, 4);
    wconv_kernel<<<wgrid, 256>>>((const float*)d_in[1], (const float*)d_in[3],
                                 (const float*)d_in[5], (const float*)d_in[7]);

    dim3 grid_qkv(DD / 128, NR / 128, 3);
    qkv_mma_kernel<<<grid_qkv, 256, QKV_DSMEM>>>(bq, bk, bv);

    dim3 grid_attn(TT / 128, BB * HH);
    attn_mma_kernel<<<grid_attn, 256, ATTN_DSMEM>>>();

    dim3 grid_out(DD / 128, NR / 128);
    out_mma_kernel<<<grid_out, 256, OUT_DSMEM>>>(x, bo, out);
}

// round 9
// speedup vs baseline: 7.4740x; 1.1106x over previous
#include <cuda_runtime.h>
#include <cuda_bf16.h>
#include <cstdint>

#define BB 4
#define TT 2048
#define DD 1024
#define HH 16
#define HD 64
#define NR (BB*TT)   // 8192

// ---------------- device scratch (allocation-free rule) ----------------
__device__ __nv_bfloat16 g_qb[NR*DD];        // [B,H,T,HD] bf16 (q pre-scaled by 0.125*log2e)
__device__ __nv_bfloat16 g_kb[NR*DD];
__device__ __nv_bfloat16 g_vb[NR*DD];
__device__ __nv_bfloat16 g_xnh[NR*DD];       // layernormed x, bf16
__device__ __nv_bfloat16 g_aoh[NR*DD];       // attention out bf16 [B*T, D]
__device__ __nv_bfloat16 g_wh[4u*DD*DD];     // Wq,Wk,Wv,Wo bf16

__device__ __forceinline__ uint32_t smem_u32(const void* p) {
    uint32_t a;
    asm("{ .reg .u64 t; cvta.to.shared.u64 t, %1; cvt.u32.u64 %0, t; }" : "=r"(a) : "l"(p));
    return a;
}
__device__ __forceinline__ uint32_t packbf(float a, float b) {
    __nv_bfloat162 t = __floats2bfloat162_rn(a, b);
    return *(uint32_t*)&t;
}

// mma / ldmatrix / cp.async helpers
__device__ __forceinline__ void mma16816(float (&c)[4], const uint32_t (&a)[4],
                                         uint32_t b0, uint32_t b1) {
    asm volatile(
        "mma.sync.aligned.m16n8k16.row.col.f32.bf16.bf16.f32 "
        "{%0,%1,%2,%3},{%4,%5,%6,%7},{%8,%9},{%0,%1,%2,%3};"
        : "+f"(c[0]), "+f"(c[1]), "+f"(c[2]), "+f"(c[3])
        : "r"(a[0]), "r"(a[1]), "r"(a[2]), "r"(a[3]), "r"(b0), "r"(b1));
}
__device__ __forceinline__ void ldm_x4(uint32_t (&r)[4], uint32_t addr) {
    asm volatile("ldmatrix.sync.aligned.m8n8.x4.shared.b16 {%0,%1,%2,%3}, [%4];"
                 : "=r"(r[0]), "=r"(r[1]), "=r"(r[2]), "=r"(r[3]) : "r"(addr));
}
__device__ __forceinline__ void ldm_x4_t(uint32_t (&r)[4], uint32_t addr) {
    asm volatile("ldmatrix.sync.aligned.m8n8.x4.trans.shared.b16 {%0,%1,%2,%3}, [%4];"
                 : "=r"(r[0]), "=r"(r[1]), "=r"(r[2]), "=r"(r[3]) : "r"(addr));
}
__device__ __forceinline__ void cp16(uint32_t s, const void* g) {
    asm volatile("cp.async.cg.shared.global [%0], [%1], 16;" :: "r"(s), "l"(g));
}
__device__ __forceinline__ void cp_commit() { asm volatile("cp.async.commit_group;"); }
__device__ __forceinline__ void cp_wait1()  { asm volatile("cp.async.wait_group 1;"); }
__device__ __forceinline__ void cp_wait0()  { asm volatile("cp.async.wait_group 0;"); }

// ---------------------------------------------------------------------------
// Weight convert: fp32 -> bf16 for Wq,Wk,Wv,Wo
// ---------------------------------------------------------------------------
__global__ void wconv_kernel(const float* __restrict__ Wq, const float* __restrict__ Wk,
                             const float* __restrict__ Wv, const float* __restrict__ Wo) {
    int m = blockIdx.y;
    const float* W = (m == 0) ? Wq : (m == 1) ? Wk : (m == 2) ? Wv : Wo;
    size_t base = (size_t)m * DD * DD;
    int idx = blockIdx.x * 256 + threadIdx.x;
    float4 v = ((const float4*)W)[idx];
    __nv_bfloat162* dh = (__nv_bfloat162*)(g_wh + base + (size_t)idx * 4);
    dh[0] = __floats2bfloat162_rn(v.x, v.y);
    dh[1] = __floats2bfloat162_rn(v.z, v.w);
}

// ---------------------------------------------------------------------------
// LayerNorm -> bf16
// ---------------------------------------------------------------------------
__global__ void ln_kernel(const float* __restrict__ x,
                          const float* __restrict__ gamma,
                          const float* __restrict__ beta) {
    int row = blockIdx.x;
    int t = threadIdx.x;
    const float4* xr = (const float4*)(x + (size_t)row * DD);
    float4 v = xr[t];
    float s  = v.x + v.y + v.z + v.w;
    float sq = v.x*v.x + v.y*v.y + v.z*v.z + v.w*v.w;

    __shared__ float red0[8], red1[8];
    #pragma unroll
    for (int o = 16; o > 0; o >>= 1) {
        s  += __shfl_xor_sync(0xffffffffu, s,  o);
        sq += __shfl_xor_sync(0xffffffffu, sq, o);
    }
    int w = t >> 5, l = t & 31;
    if (l == 0) { red0[w] = s; red1[w] = sq; }
    __syncthreads();
    __shared__ float smu, srs;
    if (t < 32) {
        float a  = (t < 8) ? red0[t] : 0.f;
        float b2 = (t < 8) ? red1[t] : 0.f;
        #pragma unroll
        for (int o = 4; o > 0; o >>= 1) {
            a  += __shfl_xor_sync(0xffffffffu, a,  o);
            b2 += __shfl_xor_sync(0xffffffffu, b2, o);
        }
        if (t == 0) {
            float mu = a * (1.0f / DD);
            float var = b2 * (1.0f / DD) - mu * mu;
            smu = mu; srs = rsqrtf(var + 1e-5f);
        }
    }
    __syncthreads();
    float mu = smu, rs = srs;
    float4 gv = ((const float4*)gamma)[t];
    float4 bv = ((const float4*)beta)[t];
    float o0 = (v.x - mu) * rs * gv.x + bv.x;
    float o1 = (v.y - mu) * rs * gv.y + bv.y;
    float o2 = (v.z - mu) * rs * gv.z + bv.z;
    float o3 = (v.w - mu) * rs * gv.w + bv.w;
    size_t off = (size_t)row * DD + t * 4;
    ((__nv_bfloat162*)(g_xnh + off))[0] = __floats2bfloat162_rn(o0, o1);
    ((__nv_bfloat162*)(g_xnh + off))[1] = __floats2bfloat162_rn(o2, o3);
}

// ---------------------------------------------------------------------------
// Tensor-core GEMM core. 128x128 tile, k-chunk 32, 8 warps 4(m)x2(n).
// 3-stage cp.async pipeline, ONE __syncthreads per chunk.
// acc = Ah @ Bh^T (1 mma). Stage: Ah, Bh (20480 B).
// ---------------------------------------------------------------------------
#define SPITCH 40            // elements per row (80 bytes)
#define GMATB  10240
#define GSTAGEB (2 * GMATB)          // 20480
#define GEMM_DSMEM (3 * GSTAGEB)     // 61440
#define NKC (DD / 32)                // 32

__device__ __forceinline__ void gemm_issue(
    const __nv_bfloat16* Ahg, const __nv_bfloat16* Bhg,
    uint32_t base, int kc, int tid)
{
    #pragma unroll
    for (int u = 0; u < 2; u++) {
        int idx = tid * 2 + u;                 // 0..511
        int row = idx >> 2;
        int sg  = idx & 3;                     // 16B segment
        uint32_t so = (uint32_t)(row * 80 + sg * 16);
        size_t ge = (size_t)row * DD + kc * 32 + sg * 8;
        cp16(base + so,         Ahg + ge);
        cp16(base + GMATB + so, Bhg + ge);
    }
    cp_commit();
}

__device__ __forceinline__ void gemm_core(
    const __nv_bfloat16* __restrict__ Ahg, const __nv_bfloat16* __restrict__ Bhg,
    char* dsm, float (&acc)[2][8][4], int tid)
{
    int lane = tid & 31;
    int w = tid >> 5;
    int wm = w & 3;
    int wn = w >> 2;

    uint32_t sb0 = smem_u32(dsm);
    int a_row = (lane & 15), a_cg = (lane >> 4) * 8;
    int quad = lane >> 3;
    int b_row = (lane & 7) + ((quad & 2) ? 8 : 0);
    int b_col = (quad & 1) ? 8 : 0;

    gemm_issue(Ahg, Bhg, sb0,           0, tid);
    gemm_issue(Ahg, Bhg, sb0 + GSTAGEB, 1, tid);

    for (int kc = 0; kc < NKC; kc++) {
        if (kc < NKC - 1) cp_wait1(); else cp_wait0();
        __syncthreads();
        if (kc + 2 < NKC)
            gemm_issue(Ahg, Bhg, sb0 + ((kc + 2) % 3) * GSTAGEB, kc + 2, tid);

        uint32_t Ah_u = sb0 + (kc % 3) * GSTAGEB;
        uint32_t Bh_u = Ah_u + GMATB;

        #pragma unroll
        for (int ks = 0; ks < 2; ks++) {
            uint32_t ah[2][4];
            #pragma unroll
            for (int mt = 0; mt < 2; mt++) {
                uint32_t off = (uint32_t)((wm * 32 + mt * 16 + a_row) * SPITCH + ks * 16 + a_cg) * 2;
                ldm_x4(ah[mt], Ah_u + off);
            }
            #pragma unroll
            for (int nt2 = 0; nt2 < 4; nt2++) {
                uint32_t boff = (uint32_t)((wn * 64 + nt2 * 16 + b_row) * SPITCH + ks * 16 + b_col) * 2;
                uint32_t bh[4];
                ldm_x4(bh, Bh_u + boff);
                int n0t = nt2 * 2, n1t = nt2 * 2 + 1;
                mma16816(acc[0][n0t], ah[0], bh[0], bh[1]);
                mma16816(acc[1][n0t], ah[1], bh[0], bh[1]);
                mma16816(acc[0][n1t], ah[0], bh[2], bh[3]);
                mma16816(acc[1][n1t], ah[1], bh[2], bh[3]);
            }
        }
    }
    __syncthreads();
}

// ---------------------------------------------------------------------------
// QKV projection -> bf16 [B,H,T,HD]; q pre-scaled by 0.125*log2e
// ---------------------------------------------------------------------------
__global__ void __launch_bounds__(256, 2) qkv_mma_kernel(
    const float* __restrict__ bq, const float* __restrict__ bk, const float* __restrict__ bv)
{
    extern __shared__ char dsm[];
    int tid = threadIdx.x;
    int z = blockIdx.z;
    int m0 = blockIdx.y * 128;
    int n0 = blockIdx.x * 128;

    const float* bias; __nv_bfloat16* dst; float sc;
    if (z == 0)      { bias = bq; dst = g_qb; sc = 0.125f * 1.44269504089f; }
    else if (z == 1) { bias = bk; dst = g_kb; sc = 1.0f; }
    else             { bias = bv; dst = g_vb; sc = 1.0f; }

    float acc[2][8][4] = {};
    gemm_core(g_xnh + (size_t)m0 * DD,
              g_wh + (size_t)z * DD * DD + (size_t)n0 * DD,
              dsm, acc, tid);

    int lane = tid & 31;
    int w = tid >> 5, wm = w & 3, wn = w >> 2;
    #pragma unroll
    for (int mt = 0; mt < 2; mt++) {
        #pragma unroll
        for (int nt = 0; nt < 8; nt++) {
            int r = m0 + wm * 32 + mt * 16 + (lane >> 2);
            int c = n0 + wn * 64 + nt * 8 + (lane & 3) * 2;
            float b0 = bias[c], b1 = bias[c + 1];
            #pragma unroll
            for (int rr = 0; rr < 2; rr++) {
                int row = r + rr * 8;
                int b = row >> 11, t = row & (TT - 1);
                int h = c >> 6, hd = c & 63;
                __nv_bfloat16* p = dst + (((size_t)(b * HH + h)) * TT + t) * HD + hd;
                float vx = (acc[mt][nt][rr * 2 + 0] + b0) * sc;
                float vy = (acc[mt][nt][rr * 2 + 1] + b1) * sc;
                *(__nv_bfloat162*)p = __floats2bfloat162_rn(vx, vy);
            }
        }
    }
}

// ---------------------------------------------------------------------------
// Output projection: out = x + ao @ Wo^T + bo   (1 mma: aoh @ Woh)
// ---------------------------------------------------------------------------
__global__ void __launch_bounds__(256, 2) out_mma_kernel(
    const float* __restrict__ x, const float* __restrict__ bo, float* __restrict__ out)
{
    extern __shared__ char dsm[];
    int tid = threadIdx.x;
    int m0 = blockIdx.y * 128;
    int n0 = blockIdx.x * 128;

    float acc[2][8][4] = {};
    gemm_core(g_aoh + (size_t)m0 * DD,
              g_wh + (size_t)3 * DD * DD + (size_t)n0 * DD,
              dsm, acc, tid);

    int lane = tid & 31;
    int w = tid >> 5, wm = w & 3, wn = w >> 2;
    #pragma unroll
    for (int mt = 0; mt < 2; mt++) {
        #pragma unroll
        for (int nt = 0; nt < 8; nt++) {
            int r = m0 + wm * 32 + mt * 16 + (lane >> 2);
            int c = n0 + wn * 64 + nt * 8 + (lane & 3) * 2;
            float b0 = bo[c], b1 = bo[c + 1];
            #pragma unroll
            for (int rr = 0; rr < 2; rr++) {
                int row = r + rr * 8;
                const float* xp = x + (size_t)row * DD + c;
                float* p = out + (size_t)row * DD + c;
                float2 xv = *(const float2*)xp;
                float2 v;
                v.x = acc[mt][nt][rr * 2 + 0] + b0 + xv.x;
                v.y = acc[mt][nt][rr * 2 + 1] + b1 + xv.y;
                *(float2*)p = v;
            }
        }
    }
}

// ---------------------------------------------------------------------------
// Tensor-core flash attention (causal), exp2-domain softmax.
// q-tile 128 (8 warps x 16 rows), k-tile 64, 3-stage cp.async K/V pipeline,
// single __syncthreads per k-tile. Warp-coherent rescale skip + masked-tile skip.
// ---------------------------------------------------------------------------
#define VPITCH 72                    // elements (144 B)
#define KVHALF (64 * VPITCH * 2)     // 9216 B
#define KVSTAGE (2 * KVHALF)         // 18432 B
#define ATTN_DSMEM (3 * KVSTAGE)     // 55296 B

__global__ void __launch_bounds__(256, 2) attn_mma_kernel() {
    extern __shared__ char kvsm[];
    __shared__ __nv_bfloat16 Qs[128 * VPITCH];

    int tid = threadIdx.x;
    int lane = tid & 31;
    int w = tid >> 5;
    int qt = gridDim.x - 1 - blockIdx.x;   // heavy tiles first
    int bh = blockIdx.y;
    int q0 = qt * 128;

    const __nv_bfloat16* Qg = g_qb + (size_t)bh * TT * HD;
    const __nv_bfloat16* Kg = g_kb + (size_t)bh * TT * HD;
    const __nv_bfloat16* Vg = g_vb + (size_t)bh * TT * HD;

    uint32_t kv0 = smem_u32(kvsm);

    auto kv_issue = [&](int kt, int s) {
        uint32_t base = kv0 + s * KVSTAGE;
        #pragma unroll
        for (int u = 0; u < 2; u++) {
            int idx = u * 256 + tid;
            int r = idx >> 3, sg = idx & 7;
            size_t ge = (size_t)(kt * 64 + r) * HD + sg * 8;
            uint32_t so = (uint32_t)(r * 144 + sg * 16);
            cp16(base + so,          Kg + ge);
            cp16(base + KVHALF + so, Vg + ge);
        }
        cp_commit();
    };

    int nkt = 2 * qt + 2;
    kv_issue(0, 0);
    kv_issue(1, 1);

    // load Q tile (128 x 64), coalesced
    #pragma unroll
    for (int u = 0; u < 4; u++) {
        int idx = u * 256 + tid;
        int r = idx >> 3, sg = (idx & 7) * 8;
        *(uint4*)(Qs + r * VPITCH + sg) = *(const uint4*)(Qg + (size_t)(q0 + r) * HD + sg);
    }

    int a_row = lane & 15, a_cg = (lane >> 4) * 8;
    uint32_t Qs_u = smem_u32(Qs);
    int quad = lane >> 3;
    int b_row = (lane & 7) + ((quad & 2) ? 8 : 0);   // non-trans (K)
    int b_col = (quad & 1) ? 8 : 0;
    int t_row = (lane & 7) + ((quad & 1) ? 8 : 0);   // trans (V)
    int t_col = (quad & 2) ? 8 : 0;

    float m_[2] = {-1e30f, -1e30f};
    float l_[2] = {0.f, 0.f};
    float o[8][4] = {};
    int r0g = q0 + w * 16 + (lane >> 2);
    int warp_max_row = q0 + w * 16 + 15;   // highest q row this warp owns

    for (int kt = 0; kt < nkt; kt++) {
        if (kt < nkt - 1) cp_wait1(); else cp_wait0();
        __syncthreads();
        if (kt + 2 < nkt) kv_issue(kt + 2, (kt + 2) % 3);

        // fully-masked tile for this warp: all P would be 0 — skip everything
        if (kt * 64 > warp_max_row) continue;

        uint32_t Ks_u = kv0 + (kt % 3) * KVSTAGE;
        uint32_t Vs_u = Ks_u + KVHALF;

        // S = Q K^T  (q already scaled -> log2 domain)
        float s_[8][4] = {};
        #pragma unroll
        for (int sk = 0; sk < 4; sk++) {
            uint32_t aq[4];
            ldm_x4(aq, Qs_u + (uint32_t)((w * 16 + a_row) * VPITCH + sk * 16 + a_cg) * 2);
            #pragma unroll
            for (int nt2 = 0; nt2 < 4; nt2++) {
                uint32_t bk[4];
                ldm_x4(bk, Ks_u + (uint32_t)((nt2 * 16 + b_row) * VPITCH + sk * 16 + b_col) * 2);
                mma16816(s_[nt2*2],   aq, bk[0], bk[1]);
                mma16816(s_[nt2*2+1], aq, bk[2], bk[3]);
            }
        }

        // causal mask
        if (kt * 64 + 63 > r0g) {
            #pragma unroll
            for (int nt = 0; nt < 8; nt++) {
                int c = kt * 64 + nt * 8 + (lane & 3) * 2;
                if (c     > r0g)     s_[nt][0] = -1e30f;
                if (c + 1 > r0g)     s_[nt][1] = -1e30f;
                if (c     > r0g + 8) s_[nt][2] = -1e30f;
                if (c + 1 > r0g + 8) s_[nt][3] = -1e30f;
            }
        }

        // online softmax in exp2 domain
        #pragma unroll
        for (int ri = 0; ri < 2; ri++) {
            float mx = -1e30f;
            #pragma unroll
            for (int nt = 0; nt < 8; nt++)
                mx = fmaxf(mx, fmaxf(s_[nt][ri*2], s_[nt][ri*2+1]));
            mx = fmaxf(mx, __shfl_xor_sync(0xffffffffu, mx, 1));
            mx = fmaxf(mx, __shfl_xor_sync(0xffffffffu, mx, 2));
            float mn = fmaxf(m_[ri], mx);
            float corr = exp2f(m_[ri] - mn);
            m_[ri] = mn;
            float rs = 0.f;
            #pragma unroll
            for (int nt = 0; nt < 8; nt++) {
                float p0 = exp2f(s_[nt][ri*2]   - mn);
                float p1 = exp2f(s_[nt][ri*2+1] - mn);
                s_[nt][ri*2] = p0; s_[nt][ri*2+1] = p1;
                rs += p0 + p1;
            }
            rs += __shfl_xor_sync(0xffffffffu, rs, 1);
            rs += __shfl_xor_sync(0xffffffffu, rs, 2);
            l_[ri] = l_[ri] * corr + rs;
            // warp-coherent skip: only rescale O when some row's max moved
            if (__any_sync(0xffffffffu, corr < 0.99999f)) {
                #pragma unroll
                for (int nt = 0; nt < 8; nt++) {
                    o[nt][ri*2]   *= corr;
                    o[nt][ri*2+1] *= corr;
                }
            }
        }

        // pack P into A-fragments
        uint32_t ap[4][4];
        #pragma unroll
        for (int j = 0; j < 4; j++) {
            ap[j][0] = packbf(s_[2*j][0],   s_[2*j][1]);
            ap[j][1] = packbf(s_[2*j][2],   s_[2*j][3]);
            ap[j][2] = packbf(s_[2*j+1][0], s_[2*j+1][1]);
            ap[j][3] = packbf(s_[2*j+1][2], s_[2*j+1][3]);
        }

        // O += P V
        #pragma unroll
        for (int j = 0; j < 4; j++) {
            #pragma unroll
            for (int dt2 = 0; dt2 < 4; dt2++) {
                uint32_t bv[4];
                ldm_x4_t(bv, Vs_u + (uint32_t)((j * 16 + t_row) * VPITCH + dt2 * 16 + t_col) * 2);
                mma16816(o[dt2*2],   ap[j], bv[0], bv[1]);
                mma16816(o[dt2*2+1], ap[j], bv[2], bv[3]);
            }
        }
    }

    // epilogue: normalize, write bf16 [B*T, D]
    int b = bh / HH, h = bh % HH;
    #pragma unroll
    for (int ri = 0; ri < 2; ri++) {
        float inv = 1.0f / l_[ri];
        int qg = q0 + w * 16 + (lane >> 2) + ri * 8;
        size_t base = ((size_t)(b * TT + qg)) * DD + h * HD;
        #pragma unroll
        for (int nt = 0; nt < 8; nt++) {
            int c = nt * 8 + (lane & 3) * 2;
            float v0 = o[nt][ri*2] * inv, v1 = o[nt][ri*2+1] * inv;
            *(__nv_bfloat162*)(g_aoh + base + c) = __floats2bfloat162_rn(v0, v1);
        }
    }
}

// ---------------------------------------------------------------------------
extern "C" void kernel_launch(void* const* d_in, const int* in_sizes, int n_in,
                              void* d_out, int out_size) {
    const float* x     = (const float*)d_in[0];
    const float* bq    = (const float*)d_in[2];
    const float* bk    = (const float*)d_in[4];
    const float* bv    = (const float*)d_in[6];
    const float* bo    = (const float*)d_in[8];
    const float* gamma = (const float*)d_in[9];
    const float* beta  = (const float*)d_in[10];
    float* out = (float*)d_out;

    cudaFuncSetAttribute(qkv_mma_kernel, cudaFuncAttributeMaxDynamicSharedMemorySize, GEMM_DSMEM);
    cudaFuncSetAttribute(out_mma_kernel, cudaFuncAttributeMaxDynamicSharedMemorySize, GEMM_DSMEM);
    cudaFuncSetAttribute(attn_mma_kernel, cudaFuncAttributeMaxDynamicSharedMemorySize, ATTN_DSMEM);

    ln_kernel<<<NR, 256>>>(x, gamma, beta);

    dim3 wgrid(1024, 4);
    wconv_kernel<<<wgrid, 256>>>((const float*)d_in[1], (const float*)d_in[3],
                                 (const float*)d_in[5], (const float*)d_in[7]);

    dim3 grid_qkv(DD / 128, NR / 128, 3);
    qkv_mma_kernel<<<grid_qkv, 256, GEMM_DSMEM>>>(bq, bk, bv);

    dim3 grid_attn(TT / 128, BB * HH);
    attn_mma_kernel<<<grid_attn, 256, ATTN_DSMEM>>>();

    dim3 grid_out(DD / 128, NR / 128);
    out_mma_kernel<<<grid_out, 256, GEMM_DSMEM>>>(x, bo, out);
}